// round 15
// baseline (speedup 1.0000x reference)
#include <cuda_runtime.h>
#include <cuda_bf16.h>
#include <math.h>
#include <stdint.h>

#define Bn 4
#define Sn 2048
#define Dn 1024
#define Hn 16
#define DKn 64
#define Mn (Bn*Sn)
#define WSZ ((size_t)Dn*Dn)

// Scratch (static device globals: allocation-free)
__device__ float g_cs[(size_t)Sn*32*2];                 // cos/sin table
__device__ __nv_bfloat16 g_ah[(size_t)Mn*Dn];
__device__ __nv_bfloat16 g_al[(size_t)Mn*Dn];
__device__ __nv_bfloat16 g_wh[4*WSZ];                   // [wq|wk|wv|wo] hi
__device__ __nv_bfloat16 g_wl[4*WSZ];                   // [wq|wk|wv|wo] lo
__device__ __nv_bfloat16 g_qh[(size_t)Bn*Hn*Sn*DKn];
__device__ __nv_bfloat16 g_ql[(size_t)Bn*Hn*Sn*DKn];
__device__ __nv_bfloat16 g_kh[(size_t)Bn*Hn*Sn*DKn];
__device__ __nv_bfloat16 g_kl[(size_t)Bn*Hn*Sn*DKn];
__device__ __nv_bfloat16 g_vh[(size_t)Bn*Hn*Sn*DKn];   // [bh][dk][s] transposed
__device__ __nv_bfloat16 g_vl[(size_t)Bn*Hn*Sn*DKn];

// ===========================================================================
// helpers
// ===========================================================================
__device__ __forceinline__ uint32_t smem_u32(const void* p) {
    uint32_t a;
    asm("{ .reg .u64 t; cvta.to.shared.u64 t, %1; cvt.u32.u64 %0, t; }"
        : "=r"(a) : "l"(p));
    return a;
}

__device__ __forceinline__ void cpasync16(uint32_t dst, const void* src) {
    asm volatile("cp.async.cg.shared.global [%0], [%1], 16;" :: "r"(dst), "l"(src));
}

__device__ __forceinline__ void ldsm4(unsigned* r, uint32_t addr) {
    asm volatile("ldmatrix.sync.aligned.m8n8.x4.shared.b16 {%0,%1,%2,%3}, [%4];"
                 : "=r"(r[0]), "=r"(r[1]), "=r"(r[2]), "=r"(r[3]) : "r"(addr));
}

__device__ __forceinline__ void mma16816(float* c, const unsigned* a, const unsigned* b) {
    asm volatile(
        "mma.sync.aligned.m16n8k16.row.col.f32.bf16.bf16.f32 "
        "{%0,%1,%2,%3}, {%4,%5,%6,%7}, {%8,%9}, {%0,%1,%2,%3};"
        : "+f"(c[0]), "+f"(c[1]), "+f"(c[2]), "+f"(c[3])
        : "r"(a[0]), "r"(a[1]), "r"(a[2]), "r"(a[3]), "r"(b[0]), "r"(b[1]));
}

__device__ __forceinline__ unsigned pack2(float x, float y) {
    __nv_bfloat162 t = __floats2bfloat162_rn(x, y);
    return *(unsigned*)&t;
}

__device__ __forceinline__ void store_split(__nv_bfloat16* H, __nv_bfloat16* L,
                                            size_t off, float a, float b) {
    unsigned hp = pack2(a, b);
    __nv_bfloat162 ht = *(__nv_bfloat162*)&hp;
    unsigned lp = pack2(a - __low2float(ht), b - __high2float(ht));
    *(unsigned*)(H + off) = hp;
    *(unsigned*)(L + off) = lp;
}

// XOR-swizzled offset within a 64B-row array: row, 16B-chunk kc (0..3)
__device__ __forceinline__ uint32_t swz64(uint32_t row, uint32_t kc) {
    return (row << 6) + ((kc ^ ((row >> 1) & 3u)) << 4);
}

// ===========================================================================
// cos/sin table
// ===========================================================================
__global__ void trig_kernel(float* cs) {
    int p = blockIdx.x * blockDim.x + threadIdx.x;
    if (p >= Sn*32) return;
    int s = p >> 5, i = p & 31;
    float freq = expf(-((float)(2*i) / (float)DKn) * 9.210340371976184f);
    float sn, c;
    sincosf((float)s * freq, &sn, &c);
    cs[p*2]   = c;
    cs[p*2+1] = sn;
}

// ===========================================================================
// split fp32 -> bf16 hi/lo (x activations)
// ===========================================================================
__global__ void split_kernel(const float* __restrict__ in,
                             __nv_bfloat16* __restrict__ hi,
                             __nv_bfloat16* __restrict__ lo, int n4) {
    int i = blockIdx.x * blockDim.x + threadIdx.x;
    if (i >= n4) return;
    float4 v = *(const float4*)(in + 4*(size_t)i);
    __nv_bfloat16 h0 = __float2bfloat16(v.x);
    __nv_bfloat16 h1 = __float2bfloat16(v.y);
    __nv_bfloat16 h2 = __float2bfloat16(v.z);
    __nv_bfloat16 h3 = __float2bfloat16(v.w);
    __nv_bfloat16 l0 = __float2bfloat16(v.x - __bfloat162float(h0));
    __nv_bfloat16 l1 = __float2bfloat16(v.y - __bfloat162float(h1));
    __nv_bfloat16 l2 = __float2bfloat16(v.z - __bfloat162float(h2));
    __nv_bfloat16 l3 = __float2bfloat16(v.w - __bfloat162float(h3));
    __nv_bfloat162* ph = (__nv_bfloat162*)(hi + 4*(size_t)i);
    __nv_bfloat162* pl = (__nv_bfloat162*)(lo + 4*(size_t)i);
    ph[0] = __nv_bfloat162(h0, h1); ph[1] = __nv_bfloat162(h2, h3);
    pl[0] = __nv_bfloat162(l0, l1); pl[1] = __nv_bfloat162(l2, l3);
}

// All 4 weight matrices in one launch
__global__ void splitw_kernel(const float* __restrict__ wq, const float* __restrict__ wk,
                              const float* __restrict__ wv, const float* __restrict__ wo,
                              __nv_bfloat16* __restrict__ hi, __nv_bfloat16* __restrict__ lo) {
    int i = blockIdx.x * blockDim.x + threadIdx.x;
    if (i >= (int)(WSZ/4)) return;
    int which = blockIdx.y;
    const float* in = which == 0 ? wq : which == 1 ? wk : which == 2 ? wv : wo;
    size_t off = (size_t)which * WSZ + 4*(size_t)i;
    float4 v = *(const float4*)(in + 4*(size_t)i);
    __nv_bfloat16 h0 = __float2bfloat16(v.x);
    __nv_bfloat16 h1 = __float2bfloat16(v.y);
    __nv_bfloat16 h2 = __float2bfloat16(v.z);
    __nv_bfloat16 h3 = __float2bfloat16(v.w);
    __nv_bfloat16 l0 = __float2bfloat16(v.x - __bfloat162float(h0));
    __nv_bfloat16 l1 = __float2bfloat16(v.y - __bfloat162float(h1));
    __nv_bfloat16 l2 = __float2bfloat16(v.z - __bfloat162float(h2));
    __nv_bfloat16 l3 = __float2bfloat16(v.w - __bfloat162float(h3));
    __nv_bfloat162* ph = (__nv_bfloat162*)(hi + off);
    __nv_bfloat162* pl = (__nv_bfloat162*)(lo + off);
    ph[0] = __nv_bfloat162(h0, h1); ph[1] = __nv_bfloat162(h2, h3);
    pl[0] = __nv_bfloat162(l0, l1); pl[1] = __nv_bfloat162(l2, l3);
}

// ===========================================================================
// Split-bf16 GEMM core. 128x64 tile, BK=32, 256 thr, 3 CTAs/SM.
// XOR-swizzled smem, 3-stage ring, mid-stage cp.async issue.
// ===========================================================================
#define A_SZ 8192              // 128 rows * 64 B
#define B_SZ 4096              // 64 rows * 64 B
#define STG (2*A_SZ + 2*B_SZ)  // 24576
#define NST 3
#define GSMEM (NST*STG)        // 73728 -> 3 CTAs/SM (216KB)

__device__ __forceinline__ void gemm_load_stage(
    uint32_t sbase, int s, int tid, int mbase, int nbase,
    const __nv_bfloat16* __restrict__ Ah, const __nv_bfloat16* __restrict__ Al,
    const __nv_bfloat16* __restrict__ Wh, const __nv_bfloat16* __restrict__ Wl) {
    uint32_t sb = sbase + (uint32_t)(s % NST) * STG;
    int k0 = s * 32;
#pragma unroll
    for (int c = tid; c < 512; c += 256) {
        uint32_t row = (uint32_t)c >> 2;
        uint32_t kc = (uint32_t)c & 3;
        uint32_t so = swz64(row, kc);
        size_t ga = (size_t)(mbase + (int)row) * Dn + k0 + (int)kc * 8;
        cpasync16(sb + so,        Ah + ga);
        cpasync16(sb + A_SZ + so, Al + ga);
    }
    {
        uint32_t row = (uint32_t)tid >> 2;
        uint32_t kc = (uint32_t)tid & 3;
        uint32_t so = swz64(row, kc);
        size_t gw = (size_t)(nbase + (int)row) * Dn + k0 + (int)kc * 8;
        cpasync16(sb + 2*A_SZ + so,        Wh + gw);
        cpasync16(sb + 2*A_SZ + B_SZ + so, Wl + gw);
    }
    asm volatile("cp.async.commit_group;" ::: "memory");
}

// one k16 chunk: ldsm + 3 term-major passes
__device__ __forceinline__ void gemm_chunk(
    uint32_t aH, uint32_t aL, uint32_t bH, uint32_t bL,
    uint32_t kc, uint32_t r15, int wm, int wn, float acc[2][4][4]) {
    unsigned Af[2][4], Bh2[2][4], Bl2[2][4];
#pragma unroll
    for (int mi = 0; mi < 2; mi++)
        ldsm4(Af[mi], aH + swz64((uint32_t)(wm + mi*16) + r15, kc));
#pragma unroll
    for (int p = 0; p < 2; p++) {
        uint32_t br = (uint32_t)(wn + p*16) + r15;
        ldsm4(Bh2[p], bH + swz64(br, kc));
        ldsm4(Bl2[p], bL + swz64(br, kc));
    }
    // pass 1: Ah*Wh
#pragma unroll
    for (int p = 0; p < 2; p++)
#pragma unroll
        for (int sub = 0; sub < 2; sub++) {
            int ni = p*2 + sub;
            unsigned bh[2] = {Bh2[p][sub], Bh2[p][sub+2]};
#pragma unroll
            for (int mi = 0; mi < 2; mi++)
                mma16816(acc[mi][ni], Af[mi], bh);
        }
    // pass 2: Ah*Wl
#pragma unroll
    for (int p = 0; p < 2; p++)
#pragma unroll
        for (int sub = 0; sub < 2; sub++) {
            int ni = p*2 + sub;
            unsigned bl[2] = {Bl2[p][sub], Bl2[p][sub+2]};
#pragma unroll
            for (int mi = 0; mi < 2; mi++)
                mma16816(acc[mi][ni], Af[mi], bl);
        }
    // reload A-lo into the SAME registers
#pragma unroll
    for (int mi = 0; mi < 2; mi++)
        ldsm4(Af[mi], aL + swz64((uint32_t)(wm + mi*16) + r15, kc));
    // pass 3: Al*Wh
#pragma unroll
    for (int p = 0; p < 2; p++)
#pragma unroll
        for (int sub = 0; sub < 2; sub++) {
            int ni = p*2 + sub;
            unsigned bh[2] = {Bh2[p][sub], Bh2[p][sub+2]};
#pragma unroll
            for (int mi = 0; mi < 2; mi++)
                mma16816(acc[mi][ni], Af[mi], bh);
        }
}

__device__ __forceinline__ void gemm_mainloop(
    uint32_t sbase, int tid, int mbase, int nbase,
    const __nv_bfloat16* __restrict__ Ah, const __nv_bfloat16* __restrict__ Al,
    const __nv_bfloat16* __restrict__ Wh, const __nv_bfloat16* __restrict__ Wl,
    float acc[2][4][4]) {
    int wid = tid >> 5, lane = tid & 31;
    int wm = (wid >> 1) * 32;
    int wn = (wid & 1) * 32;
    uint32_t r15 = (uint32_t)(lane & 15);
    uint32_t hi  = (uint32_t)(lane >> 4);

#pragma unroll
    for (int mi = 0; mi < 2; mi++)
#pragma unroll
        for (int ni = 0; ni < 4; ni++)
#pragma unroll
            for (int e = 0; e < 4; e++) acc[mi][ni][e] = 0.f;

    gemm_load_stage(sbase, 0, tid, mbase, nbase, Ah, Al, Wh, Wl);
    gemm_load_stage(sbase, 1, tid, mbase, nbase, Ah, Al, Wh, Wl);

    for (int s = 0; s < 32; s++) {
        if (s + 1 < 32)
            asm volatile("cp.async.wait_group 1;" ::: "memory");
        else
            asm volatile("cp.async.wait_group 0;" ::: "memory");
        __syncthreads();

        uint32_t sb = sbase + (uint32_t)(s % NST) * STG;
        uint32_t aH = sb, aL = sb + A_SZ;
        uint32_t bH = sb + 2*A_SZ, bL = sb + 2*A_SZ + B_SZ;

        gemm_chunk(aH, aL, bH, bL, hi + 0, r15, wm, wn, acc);
        if (s + 2 < 32)
            gemm_load_stage(sbase, s + 2, tid, mbase, nbase, Ah, Al, Wh, Wl);
        gemm_chunk(aH, aL, bH, bL, hi + 2, r15, wm, wn, acc);
    }
}

// ---------------------------------------------------------------------------
// Fused QKV projection. grid (48, 64): proj = bx>>4, nb = bx&15 (64-wide).
// ---------------------------------------------------------------------------
__global__ __launch_bounds__(256, 3) void gemm_qkv(
    const __nv_bfloat16* __restrict__ Ah, const __nv_bfloat16* __restrict__ Al,
    const __nv_bfloat16* __restrict__ Whal, const __nv_bfloat16* __restrict__ Wlal,
    const float* __restrict__ cs,
    __nv_bfloat16* __restrict__ QH, __nv_bfloat16* __restrict__ QL,
    __nv_bfloat16* __restrict__ KH, __nv_bfloat16* __restrict__ KL,
    __nv_bfloat16* __restrict__ VH, __nv_bfloat16* __restrict__ VL) {
    extern __shared__ __align__(16) char dyn[];
    uint32_t sbase = smem_u32(dyn);
    int tid = threadIdx.x;
    int proj = blockIdx.x >> 4;
    int nbase = (blockIdx.x & 15) * 64;
    int mbase = blockIdx.y * 128;

    const __nv_bfloat16* Wh = Whal + (size_t)proj * WSZ;
    const __nv_bfloat16* Wl = Wlal + (size_t)proj * WSZ;

    float acc[2][4][4];
    gemm_mainloop(sbase, tid, mbase, nbase, Ah, Al, Wh, Wl, acc);

    int wid = tid >> 5, lane = tid & 31;
    int grp = lane >> 2, t4 = lane & 3;
    int wm = (wid >> 1) * 32, wn = (wid & 1) * 32;

    if (proj == 2) {
        __syncthreads();
        float* st = (float*)dyn;               // [col][row], pitch 129
#pragma unroll
        for (int mi = 0; mi < 2; mi++)
#pragma unroll
            for (int ni = 0; ni < 4; ni++) {
                int r0 = wm + mi*16 + grp;
                int c  = wn + ni*8 + t4*2;
                st[(c  )*129 + r0    ] = acc[mi][ni][0];
                st[(c+1)*129 + r0    ] = acc[mi][ni][1];
                st[(c  )*129 + r0 + 8] = acc[mi][ni][2];
                st[(c+1)*129 + r0 + 8] = acc[mi][ni][3];
            }
        __syncthreads();
        int c  = tid >> 2;                     // 0..63 (dk within tile)
        int sh = (tid & 3) * 32;               // s-quarter
        int gcol = nbase + c;
        int h = gcol >> 6, dk = gcol & 63;
        int b = mbase >> 11, sq = mbase & (Sn-1);
        size_t base = ((size_t)((b*Hn + h)*64) + dk)*Sn + sq + sh;
        const float* row = st + c*129 + sh;
#pragma unroll
        for (int j = 0; j < 4; j++) {
            uint32_t hv[4], lv[4];
#pragma unroll
            for (int i = 0; i < 4; i++) {
                float a = row[j*8 + 2*i], bb = row[j*8 + 2*i + 1];
                hv[i] = pack2(a, bb);
                __nv_bfloat162 ht = *(__nv_bfloat162*)&hv[i];
                lv[i] = pack2(a - __low2float(ht), bb - __high2float(ht));
            }
            *(uint4*)(VH + base + j*8) = make_uint4(hv[0], hv[1], hv[2], hv[3]);
            *(uint4*)(VL + base + j*8) = make_uint4(lv[0], lv[1], lv[2], lv[3]);
        }
        return;
    }

    __nv_bfloat16* OH = (proj == 0) ? QH : KH;
    __nv_bfloat16* OL = (proj == 0) ? QL : KL;
#pragma unroll
    for (int mi = 0; mi < 2; mi++)
#pragma unroll
        for (int ni = 0; ni < 4; ni++) {
            int row0 = mbase + wm + mi*16 + grp;
            int row1 = row0 + 8;
            int col  = nbase + wn + ni*8 + t4*2;
            int h = col >> 6;
            int d = col & 63;
            int i = d >> 1;
            int s0 = row0 & (Sn-1), b0 = row0 >> 11;
            int s1 = row1 & (Sn-1), b1 = row1 >> 11;
            float2 c0 = *(const float2*)(cs + ((size_t)s0*32 + i)*2);
            float2 c1 = *(const float2*)(cs + ((size_t)s1*32 + i)*2);
            float r00 = acc[mi][ni][0]*c0.x - acc[mi][ni][1]*c0.y;
            float r01 = acc[mi][ni][0]*c0.y + acc[mi][ni][1]*c0.x;
            float r10 = acc[mi][ni][2]*c1.x - acc[mi][ni][3]*c1.y;
            float r11 = acc[mi][ni][2]*c1.y + acc[mi][ni][3]*c1.x;
            size_t off0 = ((size_t)(b0*Hn + h)*Sn + s0)*DKn + d;
            size_t off1 = ((size_t)(b1*Hn + h)*Sn + s1)*DKn + d;
            store_split(OH, OL, off0, r00, r01);
            store_split(OH, OL, off1, r10, r11);
        }
}

// ---------------------------------------------------------------------------
// Output projection: plain fp32 epilogue. grid (16, 64).
// ---------------------------------------------------------------------------
__global__ __launch_bounds__(256, 3) void gemm_out(
    const __nv_bfloat16* __restrict__ Ah, const __nv_bfloat16* __restrict__ Al,
    const __nv_bfloat16* __restrict__ Wh, const __nv_bfloat16* __restrict__ Wl,
    float* __restrict__ C) {
    extern __shared__ __align__(16) char dyn[];
    uint32_t sbase = smem_u32(dyn);
    int tid = threadIdx.x;
    int mbase = blockIdx.y * 128, nbase = blockIdx.x * 64;

    float acc[2][4][4];
    gemm_mainloop(sbase, tid, mbase, nbase, Ah, Al, Wh, Wl, acc);

    int wid = tid >> 5, lane = tid & 31;
    int grp = lane >> 2, t4 = lane & 3;
    int wm = (wid >> 1) * 32, wn = (wid & 1) * 32;
#pragma unroll
    for (int mi = 0; mi < 2; mi++)
#pragma unroll
        for (int ni = 0; ni < 4; ni++) {
            int row0 = mbase + wm + mi*16 + grp;
            int col  = nbase + wn + ni*8 + t4*2;
            *(float2*)(C + (size_t)row0 * Dn + col) =
                make_float2(acc[mi][ni][0], acc[mi][ni][1]);
            *(float2*)(C + (size_t)(row0+8) * Dn + col) =
                make_float2(acc[mi][ni][2], acc[mi][ni][3]);
        }
}

// ---------------------------------------------------------------------------
// Causal flash attention, split-bf16 MMA + ldmatrix, term-major MMA order.
// 3-stage cp.async ring (wait lag 1), next-tile load issued after QK MMAs.
// Fully-masked warp-tiles skipped (bit-exact). grid (bh=64, qtrev=16).
// ---------------------------------------------------------------------------
#define LDA 72        // halfs; byte pitch 144
#define AARR 9216     // one array: 64 rows * 144 B
#define ASTG (4*AARR)    // stage: Kh,Kl,Vh,Vl = 36864
#define ANST 3
#define AGSMEM (ANST*ASTG)  // 110592 -> 2 CTAs/SM

__device__ __forceinline__ void attn_load_tile(
    uint32_t sb, int bh, int kbase, int lr, int lc,
    const __nv_bfloat16* __restrict__ Kh, const __nv_bfloat16* __restrict__ Kl,
    const __nv_bfloat16* __restrict__ Vh, const __nv_bfloat16* __restrict__ Vl) {
#pragma unroll
    for (int rr = 0; rr < 2; rr++) {
        int row = lr + rr*32;
        uint32_t so = (uint32_t)row * 144 + (uint32_t)lc * 2;
        size_t koff = ((size_t)bh*Sn + kbase + row)*DKn + lc;
        size_t voff = ((size_t)bh*64 + row)*Sn + kbase + lc;
        cpasync16(sb + so,          Kh + koff);
        cpasync16(sb + AARR + so,   Kl + koff);
        cpasync16(sb + 2*AARR + so, Vh + voff);
        cpasync16(sb + 3*AARR + so, Vl + voff);
    }
    asm volatile("cp.async.commit_group;" ::: "memory");
}

__global__ __launch_bounds__(256, 2) void attn_mma(
    const __nv_bfloat16* __restrict__ Qh, const __nv_bfloat16* __restrict__ Ql,
    const __nv_bfloat16* __restrict__ Kh, const __nv_bfloat16* __restrict__ Kl,
    const __nv_bfloat16* __restrict__ Vh, const __nv_bfloat16* __restrict__ Vl,
    __nv_bfloat16* __restrict__ OHsplit, __nv_bfloat16* __restrict__ OLsplit) {
    extern __shared__ __align__(16) char adyn[];
    uint32_t sb0 = smem_u32(adyn);

    int tid = threadIdx.x;
    int wid = tid >> 5, lane = tid & 31;
    int grp = lane >> 2, t4 = lane & 3;
    int bh = blockIdx.x;
    int qt = (int)gridDim.y - 1 - (int)blockIdx.y;   // fat blocks first
    int qbase = qt * 128;
    int lr = tid >> 3;
    int lc = (tid & 7) * 8;

    uint32_t foff = (uint32_t)(lane & 15) * 144 + (lane >> 4) * 16;

    // ---- Stage Q fragments (reuse stage-0 K buffers, sync loads) ----
    unsigned qfh[4][4], qfl[4][4];
#pragma unroll
    for (int half = 0; half < 2; half++) {
        const __nv_bfloat16* qsh = Qh + ((size_t)bh*Sn + qbase + half*64)*DKn;
        const __nv_bfloat16* qsl = Ql + ((size_t)bh*Sn + qbase + half*64)*DKn;
#pragma unroll
        for (int rr = 0; rr < 2; rr++) {
            int row = lr + rr*32;
            uint32_t so = (uint32_t)row * 144 + (uint32_t)lc * 2;
            *(uint4*)(adyn + so)        = *(const uint4*)(qsh + row*DKn + lc);
            *(uint4*)(adyn + AARR + so) = *(const uint4*)(qsl + row*DKn + lc);
        }
        __syncthreads();
        if ((wid >> 2) == half) {
            uint32_t qoff = (uint32_t)((wid & 3)*16 + (lane & 15)) * 144 + (lane >> 4) * 16;
#pragma unroll
            for (int k4 = 0; k4 < 4; k4++) {
                ldsm4(qfh[k4], sb0 + qoff + k4*32);
                ldsm4(qfl[k4], sb0 + AARR + qoff + k4*32);
            }
        }
        __syncthreads();
    }

    int row0 = qbase + wid*16 + grp;
    int row1 = row0 + 8;
    float o[8][4];
    float m0 = -1e30f, m1 = -1e30f, l0 = 0.f, l1 = 0.f;
#pragma unroll
    for (int nt = 0; nt < 8; nt++)
#pragma unroll
        for (int e = 0; e < 4; e++) o[nt][e] = 0.f;

    const float SCALE = 0.125f;
    int ktmax = 2*qt + 2;   // always >= 2

    // preload tiles 0 and 1 (stages 0, 1)
    attn_load_tile(sb0, bh, 0, lr, lc, Kh, Kl, Vh, Vl);
    attn_load_tile(sb0 + ASTG, bh, 64, lr, lc, Kh, Kl, Vh, Vl);

    for (int kt = 0; kt < ktmax; kt++) {
        int kbase = kt * 64;
        if (kt + 1 < ktmax)
            asm volatile("cp.async.wait_group 1;" ::: "memory");
        else
            asm volatile("cp.async.wait_group 0;" ::: "memory");
        __syncthreads();

        uint32_t sb = sb0 + (uint32_t)(kt % ANST) * ASTG;
        uint32_t kH = sb, kL = sb + AARR, vH = sb + 2*AARR, vL = sb + 3*AARR;

        // Tile fully masked for this warp? (all keys > all of warp's rows)
        // Only ever true on the last tile for warps 0-3. Skipping is
        // bit-exact: masked entries contribute exact zeros and alpha=1.
        bool skip = (kbase >= qbase + wid*16 + 16);

        float sacc[8][4];
        if (!skip) {
#pragma unroll
            for (int nt = 0; nt < 8; nt++)
#pragma unroll
                for (int e = 0; e < 4; e++) sacc[nt][e] = 0.f;

#pragma unroll
            for (int k4 = 0; k4 < 4; k4++) {
                unsigned Bh[4][4], Bl[4][4];
#pragma unroll
                for (int p = 0; p < 4; p++) {
                    ldsm4(Bh[p], kH + foff + p*2304 + k4*32);
                    ldsm4(Bl[p], kL + foff + p*2304 + k4*32);
                }
#pragma unroll
                for (int p = 0; p < 4; p++)
#pragma unroll
                    for (int sub = 0; sub < 2; sub++) {
                        unsigned bh[2] = {Bh[p][sub], Bh[p][sub+2]};
                        mma16816(sacc[p*2 + sub], qfh[k4], bh);
                    }
#pragma unroll
                for (int p = 0; p < 4; p++)
#pragma unroll
                    for (int sub = 0; sub < 2; sub++) {
                        unsigned bl[2] = {Bl[p][sub], Bl[p][sub+2]};
                        mma16816(sacc[p*2 + sub], qfh[k4], bl);
                    }
#pragma unroll
                for (int p = 0; p < 4; p++)
#pragma unroll
                    for (int sub = 0; sub < 2; sub++) {
                        unsigned bh[2] = {Bh[p][sub], Bh[p][sub+2]};
                        mma16816(sacc[p*2 + sub], qfl[k4], bh);
                    }
            }
        }

        // issue tile kt+2's loads (ALL warps participate, even skipped ones)
        if (kt + 2 < ktmax)
            attn_load_tile(sb0 + (uint32_t)((kt + 2) % ANST) * ASTG, bh,
                           kbase + 128, lr, lc, Kh, Kl, Vh, Vl);

        if (!skip) {
            bool diag = (kbase + 64 > qbase + wid*16);
            float rm0 = -1e30f, rm1 = -1e30f;
#pragma unroll
            for (int nt = 0; nt < 8; nt++) {
                int key = kbase + nt*8 + t4*2;
                float s0 = sacc[nt][0]*SCALE, s1 = sacc[nt][1]*SCALE;
                float s2 = sacc[nt][2]*SCALE, s3 = sacc[nt][3]*SCALE;
                if (diag) {
                    if (key     > row0) s0 = -1e30f;
                    if (key + 1 > row0) s1 = -1e30f;
                    if (key     > row1) s2 = -1e30f;
                    if (key + 1 > row1) s3 = -1e30f;
                }
                sacc[nt][0] = s0; sacc[nt][1] = s1;
                sacc[nt][2] = s2; sacc[nt][3] = s3;
                rm0 = fmaxf(rm0, fmaxf(s0, s1));
                rm1 = fmaxf(rm1, fmaxf(s2, s3));
            }
            rm0 = fmaxf(rm0, __shfl_xor_sync(0xffffffffu, rm0, 1, 4));
            rm0 = fmaxf(rm0, __shfl_xor_sync(0xffffffffu, rm0, 2, 4));
            rm1 = fmaxf(rm1, __shfl_xor_sync(0xffffffffu, rm1, 1, 4));
            rm1 = fmaxf(rm1, __shfl_xor_sync(0xffffffffu, rm1, 2, 4));

            float mn0 = fmaxf(m0, rm0), mn1 = fmaxf(m1, rm1);
            float a0 = __expf(m0 - mn0), a1 = __expf(m1 - mn1);
            m0 = mn0; m1 = mn1;
            float rs0 = 0.f, rs1 = 0.f;
#pragma unroll
            for (int nt = 0; nt < 8; nt++) {
                float p0 = __expf(sacc[nt][0] - mn0);
                float p1 = __expf(sacc[nt][1] - mn0);
                float p2 = __expf(sacc[nt][2] - mn1);
                float p3 = __expf(sacc[nt][3] - mn1);
                sacc[nt][0] = p0; sacc[nt][1] = p1;
                sacc[nt][2] = p2; sacc[nt][3] = p3;
                rs0 += p0 + p1; rs1 += p2 + p3;
            }
            rs0 += __shfl_xor_sync(0xffffffffu, rs0, 1, 4);
            rs0 += __shfl_xor_sync(0xffffffffu, rs0, 2, 4);
            rs1 += __shfl_xor_sync(0xffffffffu, rs1, 1, 4);
            rs1 += __shfl_xor_sync(0xffffffffu, rs1, 2, 4);
            l0 = l0*a0 + rs0; l1 = l1*a1 + rs1;
#pragma unroll
            for (int nt = 0; nt < 8; nt++) {
                o[nt][0] *= a0; o[nt][1] *= a0;
                o[nt][2] *= a1; o[nt][3] *= a1;
            }

#pragma unroll
            for (int k4 = 0; k4 < 4; k4++) {
                unsigned pah[4], pal[4];
                float* c0 = sacc[2*k4];
                float* c1 = sacc[2*k4 + 1];
                pah[0] = pack2(c0[0], c0[1]);
                pah[1] = pack2(c0[2], c0[3]);
                pah[2] = pack2(c1[0], c1[1]);
                pah[3] = pack2(c1[2], c1[3]);
                {
                    __nv_bfloat162 t0 = *(__nv_bfloat162*)&pah[0];
                    __nv_bfloat162 t1 = *(__nv_bfloat162*)&pah[1];
                    __nv_bfloat162 t2 = *(__nv_bfloat162*)&pah[2];
                    __nv_bfloat162 t3 = *(__nv_bfloat162*)&pah[3];
                    pal[0] = pack2(c0[0]-__low2float(t0), c0[1]-__high2float(t0));
                    pal[1] = pack2(c0[2]-__low2float(t1), c0[3]-__high2float(t1));
                    pal[2] = pack2(c1[0]-__low2float(t2), c1[1]-__high2float(t2));
                    pal[3] = pack2(c1[2]-__low2float(t3), c1[3]-__high2float(t3));
                }
                unsigned Vbh[4][4], Vbl[4][4];
#pragma unroll
                for (int p = 0; p < 4; p++) {
                    ldsm4(Vbh[p], vH + foff + p*2304 + k4*32);
                    ldsm4(Vbl[p], vL + foff + p*2304 + k4*32);
                }
#pragma unroll
                for (int p = 0; p < 4; p++)
#pragma unroll
                    for (int sub = 0; sub < 2; sub++) {
                        unsigned bh[2] = {Vbh[p][sub], Vbh[p][sub+2]};
                        mma16816(o[p*2 + sub], pah, bh);
                    }
#pragma unroll
                for (int p = 0; p < 4; p++)
#pragma unroll
                    for (int sub = 0; sub < 2; sub++) {
                        unsigned bl[2] = {Vbl[p][sub], Vbl[p][sub+2]};
                        mma16816(o[p*2 + sub], pah, bl);
                    }
#pragma unroll
                for (int p = 0; p < 4; p++)
#pragma unroll
                    for (int sub = 0; sub < 2; sub++) {
                        unsigned bh[2] = {Vbh[p][sub], Vbh[p][sub+2]};
                        mma16816(o[p*2 + sub], pal, bh);
                    }
            }
        }
    }

    int b = bh >> 4, h = bh & 15;
    float inv0 = 1.f / l0, inv1 = 1.f / l1;
#pragma unroll
    for (int nt = 0; nt < 8; nt++) {
        int col = h*DKn + nt*8 + t4*2;
        size_t off0 = ((size_t)b*Sn + row0)*Dn + col;
        size_t off1 = ((size_t)b*Sn + row1)*Dn + col;
        store_split(OHsplit, OLsplit, off0, o[nt][0]*inv0, o[nt][1]*inv0);
        store_split(OHsplit, OLsplit, off1, o[nt][2]*inv1, o[nt][3]*inv1);
    }
}

// ---------------------------------------------------------------------------
extern "C" void kernel_launch(void* const* d_in, const int* in_sizes, int n_in,
                              void* d_out, int out_size) {
    const float* x  = (const float*)d_in[0];
    const float* wq = (const float*)d_in[2];
    const float* wk = (const float*)d_in[3];
    const float* wv = (const float*)d_in[4];
    const float* wo = (const float*)d_in[5];
    float* out = (float*)d_out;

    float *cs;
    __nv_bfloat16 *ah, *al, *wh, *wl, *qh, *ql, *kh, *kl, *vh, *vl;
    cudaGetSymbolAddress((void**)&cs, g_cs);
    cudaGetSymbolAddress((void**)&ah, g_ah);
    cudaGetSymbolAddress((void**)&al, g_al);
    cudaGetSymbolAddress((void**)&wh, g_wh);
    cudaGetSymbolAddress((void**)&wl, g_wl);
    cudaGetSymbolAddress((void**)&qh, g_qh);
    cudaGetSymbolAddress((void**)&ql, g_ql);
    cudaGetSymbolAddress((void**)&kh, g_kh);
    cudaGetSymbolAddress((void**)&kl, g_kl);
    cudaGetSymbolAddress((void**)&vh, g_vh);
    cudaGetSymbolAddress((void**)&vl, g_vl);

    static bool attr_set = false;
    if (!attr_set) {
        cudaFuncSetAttribute(gemm_qkv,
                             cudaFuncAttributeMaxDynamicSharedMemorySize, GSMEM);
        cudaFuncSetAttribute(gemm_out,
                             cudaFuncAttributeMaxDynamicSharedMemorySize, GSMEM);
        cudaFuncSetAttribute(attn_mma,
                             cudaFuncAttributeMaxDynamicSharedMemorySize, AGSMEM);
        attr_set = true;
    }

    int xn4 = Mn*Dn/4, wn4 = (int)(WSZ/4);

    trig_kernel<<<(Sn*32 + 255)/256, 256>>>(cs);
    split_kernel<<<(xn4 + 255)/256, 256>>>(x, ah, al, xn4);
    splitw_kernel<<<dim3((wn4 + 255)/256, 4), 256>>>(wq, wk, wv, wo, wh, wl);

    gemm_qkv<<<dim3(48, Mn/128), 256, GSMEM>>>(ah, al, wh, wl, cs,
                                               qh, ql, kh, kl, vh, vl);

    attn_mma<<<dim3(Bn*Hn, Sn/128), 256, AGSMEM>>>(qh, ql, kh, kl, vh, vl, ah, al);

    gemm_out<<<dim3(Dn/64, Mn/128), 256, GSMEM>>>(ah, al, wh + 3*WSZ, wl + 3*WSZ, out);
}

// round 16
// speedup vs baseline: 1.0275x; 1.0275x over previous
#include <cuda_runtime.h>
#include <cuda_bf16.h>
#include <math.h>
#include <stdint.h>

#define Bn 4
#define Sn 2048
#define Dn 1024
#define Hn 16
#define DKn 64
#define Mn (Bn*Sn)
#define WSZ ((size_t)Dn*Dn)

// Scratch (static device globals: allocation-free)
__device__ float g_cs[(size_t)Sn*32*2];                 // cos/sin table
__device__ __nv_bfloat16 g_ah[(size_t)Mn*Dn];
__device__ __nv_bfloat16 g_al[(size_t)Mn*Dn];
__device__ __nv_bfloat16 g_wh[4*WSZ];                   // [wq|wk|wv|wo] hi
__device__ __nv_bfloat16 g_wl[4*WSZ];                   // [wq|wk|wv|wo] lo
__device__ __nv_bfloat16 g_qh[(size_t)Bn*Hn*Sn*DKn];
__device__ __nv_bfloat16 g_ql[(size_t)Bn*Hn*Sn*DKn];
__device__ __nv_bfloat16 g_kh[(size_t)Bn*Hn*Sn*DKn];
__device__ __nv_bfloat16 g_kl[(size_t)Bn*Hn*Sn*DKn];
__device__ __nv_bfloat16 g_vh[(size_t)Bn*Hn*Sn*DKn];   // [bh][dk][s] transposed
__device__ __nv_bfloat16 g_vl[(size_t)Bn*Hn*Sn*DKn];

// ===========================================================================
// helpers
// ===========================================================================
__device__ __forceinline__ uint32_t smem_u32(const void* p) {
    uint32_t a;
    asm("{ .reg .u64 t; cvta.to.shared.u64 t, %1; cvt.u32.u64 %0, t; }"
        : "=r"(a) : "l"(p));
    return a;
}

__device__ __forceinline__ void cpasync16(uint32_t dst, const void* src) {
    asm volatile("cp.async.cg.shared.global [%0], [%1], 16;" :: "r"(dst), "l"(src));
}

__device__ __forceinline__ void ldsm4(unsigned* r, uint32_t addr) {
    asm volatile("ldmatrix.sync.aligned.m8n8.x4.shared.b16 {%0,%1,%2,%3}, [%4];"
                 : "=r"(r[0]), "=r"(r[1]), "=r"(r[2]), "=r"(r[3]) : "r"(addr));
}

__device__ __forceinline__ void mma16816(float* c, const unsigned* a, const unsigned* b) {
    asm volatile(
        "mma.sync.aligned.m16n8k16.row.col.f32.bf16.bf16.f32 "
        "{%0,%1,%2,%3}, {%4,%5,%6,%7}, {%8,%9}, {%0,%1,%2,%3};"
        : "+f"(c[0]), "+f"(c[1]), "+f"(c[2]), "+f"(c[3])
        : "r"(a[0]), "r"(a[1]), "r"(a[2]), "r"(a[3]), "r"(b[0]), "r"(b[1]));
}

__device__ __forceinline__ unsigned pack2(float x, float y) {
    __nv_bfloat162 t = __floats2bfloat162_rn(x, y);
    return *(unsigned*)&t;
}

__device__ __forceinline__ void store_split(__nv_bfloat16* H, __nv_bfloat16* L,
                                            size_t off, float a, float b) {
    unsigned hp = pack2(a, b);
    __nv_bfloat162 ht = *(__nv_bfloat162*)&hp;
    unsigned lp = pack2(a - __low2float(ht), b - __high2float(ht));
    *(unsigned*)(H + off) = hp;
    *(unsigned*)(L + off) = lp;
}

// XOR-swizzled offset within a 64B-row array: row, 16B-chunk kc (0..3)
__device__ __forceinline__ uint32_t swz64(uint32_t row, uint32_t kc) {
    return (row << 6) + ((kc ^ ((row >> 1) & 3u)) << 4);
}

// ===========================================================================
// Fused preprocessing: x split (8192 blocks) | 4 weight splits (4096 blocks)
// | trig table (256 blocks). One launch.
// ===========================================================================
#define PB_X 8192
#define PB_W 4096
#define PB_T 256
#define PREP_BLOCKS (PB_X + PB_W + PB_T)

__device__ __forceinline__ void split4(const float* __restrict__ in, size_t i,
                                       __nv_bfloat16* __restrict__ hi,
                                       __nv_bfloat16* __restrict__ lo, size_t off) {
    float4 v = *(const float4*)(in + 4*i);
    __nv_bfloat16 h0 = __float2bfloat16(v.x);
    __nv_bfloat16 h1 = __float2bfloat16(v.y);
    __nv_bfloat16 h2 = __float2bfloat16(v.z);
    __nv_bfloat16 h3 = __float2bfloat16(v.w);
    __nv_bfloat16 l0 = __float2bfloat16(v.x - __bfloat162float(h0));
    __nv_bfloat16 l1 = __float2bfloat16(v.y - __bfloat162float(h1));
    __nv_bfloat16 l2 = __float2bfloat16(v.z - __bfloat162float(h2));
    __nv_bfloat16 l3 = __float2bfloat16(v.w - __bfloat162float(h3));
    __nv_bfloat162* ph = (__nv_bfloat162*)(hi + off);
    __nv_bfloat162* pl = (__nv_bfloat162*)(lo + off);
    ph[0] = __nv_bfloat162(h0, h1); ph[1] = __nv_bfloat162(h2, h3);
    pl[0] = __nv_bfloat162(l0, l1); pl[1] = __nv_bfloat162(l2, l3);
}

__global__ void prep_kernel(const float* __restrict__ x,
                            const float* __restrict__ wq, const float* __restrict__ wk,
                            const float* __restrict__ wv, const float* __restrict__ wo,
                            float* __restrict__ cs,
                            __nv_bfloat16* __restrict__ ah, __nv_bfloat16* __restrict__ al,
                            __nv_bfloat16* __restrict__ wh, __nv_bfloat16* __restrict__ wl) {
    int blk = blockIdx.x;
    if (blk < PB_X) {
        size_t i = (size_t)blk * 256 + threadIdx.x;       // < Mn*Dn/4
        split4(x, i, ah, al, 4*i);
    } else if (blk < PB_X + PB_W) {
        int r = blk - PB_X;
        int which = r >> 10;                              // 1024 blocks per matrix
        size_t i = (size_t)(r & 1023) * 256 + threadIdx.x; // < WSZ/4
        const float* in = which == 0 ? wq : which == 1 ? wk : which == 2 ? wv : wo;
        split4(in, i, wh, wl, (size_t)which * WSZ + 4*i);
    } else {
        int p = (blk - PB_X - PB_W) * 256 + threadIdx.x;
        if (p < Sn*32) {
            int s = p >> 5, i = p & 31;
            float freq = expf(-((float)(2*i) / (float)DKn) * 9.210340371976184f);
            float sn, c;
            sincosf((float)s * freq, &sn, &c);
            cs[p*2]   = c;
            cs[p*2+1] = sn;
        }
    }
}

// ===========================================================================
// Split-bf16 GEMM core. 128x64 tile, BK=32, 256 thr, 3 CTAs/SM.
// XOR-swizzled smem, 3-stage ring, mid-stage cp.async issue.
// ===========================================================================
#define A_SZ 8192              // 128 rows * 64 B
#define B_SZ 4096              // 64 rows * 64 B
#define STG (2*A_SZ + 2*B_SZ)  // 24576
#define NST 3
#define GSMEM (NST*STG)        // 73728 -> 3 CTAs/SM (216KB)

__device__ __forceinline__ void gemm_load_stage(
    uint32_t sbase, int s, int tid, int mbase, int nbase,
    const __nv_bfloat16* __restrict__ Ah, const __nv_bfloat16* __restrict__ Al,
    const __nv_bfloat16* __restrict__ Wh, const __nv_bfloat16* __restrict__ Wl) {
    uint32_t sb = sbase + (uint32_t)(s % NST) * STG;
    int k0 = s * 32;
#pragma unroll
    for (int c = tid; c < 512; c += 256) {
        uint32_t row = (uint32_t)c >> 2;
        uint32_t kc = (uint32_t)c & 3;
        uint32_t so = swz64(row, kc);
        size_t ga = (size_t)(mbase + (int)row) * Dn + k0 + (int)kc * 8;
        cpasync16(sb + so,        Ah + ga);
        cpasync16(sb + A_SZ + so, Al + ga);
    }
    {
        uint32_t row = (uint32_t)tid >> 2;
        uint32_t kc = (uint32_t)tid & 3;
        uint32_t so = swz64(row, kc);
        size_t gw = (size_t)(nbase + (int)row) * Dn + k0 + (int)kc * 8;
        cpasync16(sb + 2*A_SZ + so,        Wh + gw);
        cpasync16(sb + 2*A_SZ + B_SZ + so, Wl + gw);
    }
    asm volatile("cp.async.commit_group;" ::: "memory");
}

// one k16 chunk: ldsm + 3 term-major passes
__device__ __forceinline__ void gemm_chunk(
    uint32_t aH, uint32_t aL, uint32_t bH, uint32_t bL,
    uint32_t kc, uint32_t r15, int wm, int wn, float acc[2][4][4]) {
    unsigned Af[2][4], Bh2[2][4], Bl2[2][4];
#pragma unroll
    for (int mi = 0; mi < 2; mi++)
        ldsm4(Af[mi], aH + swz64((uint32_t)(wm + mi*16) + r15, kc));
#pragma unroll
    for (int p = 0; p < 2; p++) {
        uint32_t br = (uint32_t)(wn + p*16) + r15;
        ldsm4(Bh2[p], bH + swz64(br, kc));
        ldsm4(Bl2[p], bL + swz64(br, kc));
    }
    // pass 1: Ah*Wh
#pragma unroll
    for (int p = 0; p < 2; p++)
#pragma unroll
        for (int sub = 0; sub < 2; sub++) {
            int ni = p*2 + sub;
            unsigned bh[2] = {Bh2[p][sub], Bh2[p][sub+2]};
#pragma unroll
            for (int mi = 0; mi < 2; mi++)
                mma16816(acc[mi][ni], Af[mi], bh);
        }
    // pass 2: Ah*Wl
#pragma unroll
    for (int p = 0; p < 2; p++)
#pragma unroll
        for (int sub = 0; sub < 2; sub++) {
            int ni = p*2 + sub;
            unsigned bl[2] = {Bl2[p][sub], Bl2[p][sub+2]};
#pragma unroll
            for (int mi = 0; mi < 2; mi++)
                mma16816(acc[mi][ni], Af[mi], bl);
        }
    // reload A-lo into the SAME registers
#pragma unroll
    for (int mi = 0; mi < 2; mi++)
        ldsm4(Af[mi], aL + swz64((uint32_t)(wm + mi*16) + r15, kc));
    // pass 3: Al*Wh
#pragma unroll
    for (int p = 0; p < 2; p++)
#pragma unroll
        for (int sub = 0; sub < 2; sub++) {
            int ni = p*2 + sub;
            unsigned bh[2] = {Bh2[p][sub], Bh2[p][sub+2]};
#pragma unroll
            for (int mi = 0; mi < 2; mi++)
                mma16816(acc[mi][ni], Af[mi], bh);
        }
}

__device__ __forceinline__ void gemm_mainloop(
    uint32_t sbase, int tid, int mbase, int nbase,
    const __nv_bfloat16* __restrict__ Ah, const __nv_bfloat16* __restrict__ Al,
    const __nv_bfloat16* __restrict__ Wh, const __nv_bfloat16* __restrict__ Wl,
    float acc[2][4][4]) {
    int wid = tid >> 5, lane = tid & 31;
    int wm = (wid >> 1) * 32;
    int wn = (wid & 1) * 32;
    uint32_t r15 = (uint32_t)(lane & 15);
    uint32_t hi  = (uint32_t)(lane >> 4);

#pragma unroll
    for (int mi = 0; mi < 2; mi++)
#pragma unroll
        for (int ni = 0; ni < 4; ni++)
#pragma unroll
            for (int e = 0; e < 4; e++) acc[mi][ni][e] = 0.f;

    gemm_load_stage(sbase, 0, tid, mbase, nbase, Ah, Al, Wh, Wl);
    gemm_load_stage(sbase, 1, tid, mbase, nbase, Ah, Al, Wh, Wl);

    for (int s = 0; s < 32; s++) {
        if (s + 1 < 32)
            asm volatile("cp.async.wait_group 1;" ::: "memory");
        else
            asm volatile("cp.async.wait_group 0;" ::: "memory");
        __syncthreads();

        uint32_t sb = sbase + (uint32_t)(s % NST) * STG;
        uint32_t aH = sb, aL = sb + A_SZ;
        uint32_t bH = sb + 2*A_SZ, bL = sb + 2*A_SZ + B_SZ;

        gemm_chunk(aH, aL, bH, bL, hi + 0, r15, wm, wn, acc);
        if (s + 2 < 32)
            gemm_load_stage(sbase, s + 2, tid, mbase, nbase, Ah, Al, Wh, Wl);
        gemm_chunk(aH, aL, bH, bL, hi + 2, r15, wm, wn, acc);
    }
}

// ---------------------------------------------------------------------------
// Fused QKV projection. grid (48, 64): proj = bx>>4, nb = bx&15 (64-wide).
// ---------------------------------------------------------------------------
__global__ __launch_bounds__(256, 3) void gemm_qkv(
    const __nv_bfloat16* __restrict__ Ah, const __nv_bfloat16* __restrict__ Al,
    const __nv_bfloat16* __restrict__ Whal, const __nv_bfloat16* __restrict__ Wlal,
    const float* __restrict__ cs,
    __nv_bfloat16* __restrict__ QH, __nv_bfloat16* __restrict__ QL,
    __nv_bfloat16* __restrict__ KH, __nv_bfloat16* __restrict__ KL,
    __nv_bfloat16* __restrict__ VH, __nv_bfloat16* __restrict__ VL) {
    extern __shared__ __align__(16) char dyn[];
    uint32_t sbase = smem_u32(dyn);
    int tid = threadIdx.x;
    int proj = blockIdx.x >> 4;
    int nbase = (blockIdx.x & 15) * 64;
    int mbase = blockIdx.y * 128;

    const __nv_bfloat16* Wh = Whal + (size_t)proj * WSZ;
    const __nv_bfloat16* Wl = Wlal + (size_t)proj * WSZ;

    float acc[2][4][4];
    gemm_mainloop(sbase, tid, mbase, nbase, Ah, Al, Wh, Wl, acc);

    int wid = tid >> 5, lane = tid & 31;
    int grp = lane >> 2, t4 = lane & 3;
    int wm = (wid >> 1) * 32, wn = (wid & 1) * 32;

    if (proj == 2) {
        __syncthreads();
        float* st = (float*)dyn;               // [col][row], pitch 129
#pragma unroll
        for (int mi = 0; mi < 2; mi++)
#pragma unroll
            for (int ni = 0; ni < 4; ni++) {
                int r0 = wm + mi*16 + grp;
                int c  = wn + ni*8 + t4*2;
                st[(c  )*129 + r0    ] = acc[mi][ni][0];
                st[(c+1)*129 + r0    ] = acc[mi][ni][1];
                st[(c  )*129 + r0 + 8] = acc[mi][ni][2];
                st[(c+1)*129 + r0 + 8] = acc[mi][ni][3];
            }
        __syncthreads();
        int c  = tid >> 2;                     // 0..63 (dk within tile)
        int sh = (tid & 3) * 32;               // s-quarter
        int gcol = nbase + c;
        int h = gcol >> 6, dk = gcol & 63;
        int b = mbase >> 11, sq = mbase & (Sn-1);
        size_t base = ((size_t)((b*Hn + h)*64) + dk)*Sn + sq + sh;
        const float* row = st + c*129 + sh;
#pragma unroll
        for (int j = 0; j < 4; j++) {
            uint32_t hv[4], lv[4];
#pragma unroll
            for (int i = 0; i < 4; i++) {
                float a = row[j*8 + 2*i], bb = row[j*8 + 2*i + 1];
                hv[i] = pack2(a, bb);
                __nv_bfloat162 ht = *(__nv_bfloat162*)&hv[i];
                lv[i] = pack2(a - __low2float(ht), bb - __high2float(ht));
            }
            *(uint4*)(VH + base + j*8) = make_uint4(hv[0], hv[1], hv[2], hv[3]);
            *(uint4*)(VL + base + j*8) = make_uint4(lv[0], lv[1], lv[2], lv[3]);
        }
        return;
    }

    __nv_bfloat16* OH = (proj == 0) ? QH : KH;
    __nv_bfloat16* OL = (proj == 0) ? QL : KL;
#pragma unroll
    for (int mi = 0; mi < 2; mi++)
#pragma unroll
        for (int ni = 0; ni < 4; ni++) {
            int row0 = mbase + wm + mi*16 + grp;
            int row1 = row0 + 8;
            int col  = nbase + wn + ni*8 + t4*2;
            int h = col >> 6;
            int d = col & 63;
            int i = d >> 1;
            int s0 = row0 & (Sn-1), b0 = row0 >> 11;
            int s1 = row1 & (Sn-1), b1 = row1 >> 11;
            float2 c0 = *(const float2*)(cs + ((size_t)s0*32 + i)*2);
            float2 c1 = *(const float2*)(cs + ((size_t)s1*32 + i)*2);
            float r00 = acc[mi][ni][0]*c0.x - acc[mi][ni][1]*c0.y;
            float r01 = acc[mi][ni][0]*c0.y + acc[mi][ni][1]*c0.x;
            float r10 = acc[mi][ni][2]*c1.x - acc[mi][ni][3]*c1.y;
            float r11 = acc[mi][ni][2]*c1.y + acc[mi][ni][3]*c1.x;
            size_t off0 = ((size_t)(b0*Hn + h)*Sn + s0)*DKn + d;
            size_t off1 = ((size_t)(b1*Hn + h)*Sn + s1)*DKn + d;
            store_split(OH, OL, off0, r00, r01);
            store_split(OH, OL, off1, r10, r11);
        }
}

// ---------------------------------------------------------------------------
// Output projection: plain fp32 epilogue. grid (16, 64).
// ---------------------------------------------------------------------------
__global__ __launch_bounds__(256, 3) void gemm_out(
    const __nv_bfloat16* __restrict__ Ah, const __nv_bfloat16* __restrict__ Al,
    const __nv_bfloat16* __restrict__ Wh, const __nv_bfloat16* __restrict__ Wl,
    float* __restrict__ C) {
    extern __shared__ __align__(16) char dyn[];
    uint32_t sbase = smem_u32(dyn);
    int tid = threadIdx.x;
    int mbase = blockIdx.y * 128, nbase = blockIdx.x * 64;

    float acc[2][4][4];
    gemm_mainloop(sbase, tid, mbase, nbase, Ah, Al, Wh, Wl, acc);

    int wid = tid >> 5, lane = tid & 31;
    int grp = lane >> 2, t4 = lane & 3;
    int wm = (wid >> 1) * 32, wn = (wid & 1) * 32;
#pragma unroll
    for (int mi = 0; mi < 2; mi++)
#pragma unroll
        for (int ni = 0; ni < 4; ni++) {
            int row0 = mbase + wm + mi*16 + grp;
            int col  = nbase + wn + ni*8 + t4*2;
            *(float2*)(C + (size_t)row0 * Dn + col) =
                make_float2(acc[mi][ni][0], acc[mi][ni][1]);
            *(float2*)(C + (size_t)(row0+8) * Dn + col) =
                make_float2(acc[mi][ni][2], acc[mi][ni][3]);
        }
}

// ---------------------------------------------------------------------------
// Causal flash attention, split-bf16 MMA + ldmatrix, term-major MMA order.
// 3-stage cp.async ring (wait lag 1), next-tile load issued after QK MMAs.
// grid (bh=64, qtrev=16).
// ---------------------------------------------------------------------------
#define LDA 72        // halfs; byte pitch 144
#define AARR 9216     // one array: 64 rows * 144 B
#define ASTG (4*AARR)    // stage: Kh,Kl,Vh,Vl = 36864
#define ANST 3
#define AGSMEM (ANST*ASTG)  // 110592 -> 2 CTAs/SM

__device__ __forceinline__ void attn_load_tile(
    uint32_t sb, int bh, int kbase, int lr, int lc,
    const __nv_bfloat16* __restrict__ Kh, const __nv_bfloat16* __restrict__ Kl,
    const __nv_bfloat16* __restrict__ Vh, const __nv_bfloat16* __restrict__ Vl) {
#pragma unroll
    for (int rr = 0; rr < 2; rr++) {
        int row = lr + rr*32;
        uint32_t so = (uint32_t)row * 144 + (uint32_t)lc * 2;
        size_t koff = ((size_t)bh*Sn + kbase + row)*DKn + lc;
        size_t voff = ((size_t)bh*64 + row)*Sn + kbase + lc;
        cpasync16(sb + so,          Kh + koff);
        cpasync16(sb + AARR + so,   Kl + koff);
        cpasync16(sb + 2*AARR + so, Vh + voff);
        cpasync16(sb + 3*AARR + so, Vl + voff);
    }
    asm volatile("cp.async.commit_group;" ::: "memory");
}

__global__ __launch_bounds__(256, 2) void attn_mma(
    const __nv_bfloat16* __restrict__ Qh, const __nv_bfloat16* __restrict__ Ql,
    const __nv_bfloat16* __restrict__ Kh, const __nv_bfloat16* __restrict__ Kl,
    const __nv_bfloat16* __restrict__ Vh, const __nv_bfloat16* __restrict__ Vl,
    __nv_bfloat16* __restrict__ OHsplit, __nv_bfloat16* __restrict__ OLsplit) {
    extern __shared__ __align__(16) char adyn[];
    uint32_t sb0 = smem_u32(adyn);

    int tid = threadIdx.x;
    int wid = tid >> 5, lane = tid & 31;
    int grp = lane >> 2, t4 = lane & 3;
    int bh = blockIdx.x;
    int qt = (int)gridDim.y - 1 - (int)blockIdx.y;   // fat blocks first
    int qbase = qt * 128;
    int lr = tid >> 3;
    int lc = (tid & 7) * 8;

    uint32_t foff = (uint32_t)(lane & 15) * 144 + (lane >> 4) * 16;

    // ---- Stage Q fragments (reuse stage-0 K buffers, sync loads) ----
    unsigned qfh[4][4], qfl[4][4];
#pragma unroll
    for (int half = 0; half < 2; half++) {
        const __nv_bfloat16* qsh = Qh + ((size_t)bh*Sn + qbase + half*64)*DKn;
        const __nv_bfloat16* qsl = Ql + ((size_t)bh*Sn + qbase + half*64)*DKn;
#pragma unroll
        for (int rr = 0; rr < 2; rr++) {
            int row = lr + rr*32;
            uint32_t so = (uint32_t)row * 144 + (uint32_t)lc * 2;
            *(uint4*)(adyn + so)        = *(const uint4*)(qsh + row*DKn + lc);
            *(uint4*)(adyn + AARR + so) = *(const uint4*)(qsl + row*DKn + lc);
        }
        __syncthreads();
        if ((wid >> 2) == half) {
            uint32_t qoff = (uint32_t)((wid & 3)*16 + (lane & 15)) * 144 + (lane >> 4) * 16;
#pragma unroll
            for (int k4 = 0; k4 < 4; k4++) {
                ldsm4(qfh[k4], sb0 + qoff + k4*32);
                ldsm4(qfl[k4], sb0 + AARR + qoff + k4*32);
            }
        }
        __syncthreads();
    }

    int row0 = qbase + wid*16 + grp;
    int row1 = row0 + 8;
    float o[8][4];
    float m0 = -1e30f, m1 = -1e30f, l0 = 0.f, l1 = 0.f;
#pragma unroll
    for (int nt = 0; nt < 8; nt++)
#pragma unroll
        for (int e = 0; e < 4; e++) o[nt][e] = 0.f;

    const float SCALE = 0.125f;
    int ktmax = 2*qt + 2;   // always >= 2

    // preload tiles 0 and 1 (stages 0, 1)
    attn_load_tile(sb0, bh, 0, lr, lc, Kh, Kl, Vh, Vl);
    attn_load_tile(sb0 + ASTG, bh, 64, lr, lc, Kh, Kl, Vh, Vl);

    for (int kt = 0; kt < ktmax; kt++) {
        int kbase = kt * 64;
        if (kt + 1 < ktmax)
            asm volatile("cp.async.wait_group 1;" ::: "memory");
        else
            asm volatile("cp.async.wait_group 0;" ::: "memory");
        __syncthreads();

        uint32_t sb = sb0 + (uint32_t)(kt % ANST) * ASTG;
        uint32_t kH = sb, kL = sb + AARR, vH = sb + 2*AARR, vL = sb + 3*AARR;

        float sacc[8][4];
#pragma unroll
        for (int nt = 0; nt < 8; nt++)
#pragma unroll
            for (int e = 0; e < 4; e++) sacc[nt][e] = 0.f;

#pragma unroll
        for (int k4 = 0; k4 < 4; k4++) {
            unsigned Bh[4][4], Bl[4][4];
#pragma unroll
            for (int p = 0; p < 4; p++) {
                ldsm4(Bh[p], kH + foff + p*2304 + k4*32);
                ldsm4(Bl[p], kL + foff + p*2304 + k4*32);
            }
#pragma unroll
            for (int p = 0; p < 4; p++)
#pragma unroll
                for (int sub = 0; sub < 2; sub++) {
                    unsigned bh[2] = {Bh[p][sub], Bh[p][sub+2]};
                    mma16816(sacc[p*2 + sub], qfh[k4], bh);
                }
#pragma unroll
            for (int p = 0; p < 4; p++)
#pragma unroll
                for (int sub = 0; sub < 2; sub++) {
                    unsigned bl[2] = {Bl[p][sub], Bl[p][sub+2]};
                    mma16816(sacc[p*2 + sub], qfh[k4], bl);
                }
#pragma unroll
            for (int p = 0; p < 4; p++)
#pragma unroll
                for (int sub = 0; sub < 2; sub++) {
                    unsigned bh[2] = {Bh[p][sub], Bh[p][sub+2]};
                    mma16816(sacc[p*2 + sub], qfl[k4], bh);
                }
        }

        // issue tile kt+2's loads: overlaps softmax + PV below.
        if (kt + 2 < ktmax)
            attn_load_tile(sb0 + (uint32_t)((kt + 2) % ANST) * ASTG, bh,
                           kbase + 128, lr, lc, Kh, Kl, Vh, Vl);

        bool diag = (kbase + 64 > qbase + wid*16);
        float rm0 = -1e30f, rm1 = -1e30f;
#pragma unroll
        for (int nt = 0; nt < 8; nt++) {
            int key = kbase + nt*8 + t4*2;
            float s0 = sacc[nt][0]*SCALE, s1 = sacc[nt][1]*SCALE;
            float s2 = sacc[nt][2]*SCALE, s3 = sacc[nt][3]*SCALE;
            if (diag) {
                if (key     > row0) s0 = -1e30f;
                if (key + 1 > row0) s1 = -1e30f;
                if (key     > row1) s2 = -1e30f;
                if (key + 1 > row1) s3 = -1e30f;
            }
            sacc[nt][0] = s0; sacc[nt][1] = s1;
            sacc[nt][2] = s2; sacc[nt][3] = s3;
            rm0 = fmaxf(rm0, fmaxf(s0, s1));
            rm1 = fmaxf(rm1, fmaxf(s2, s3));
        }
        rm0 = fmaxf(rm0, __shfl_xor_sync(0xffffffffu, rm0, 1, 4));
        rm0 = fmaxf(rm0, __shfl_xor_sync(0xffffffffu, rm0, 2, 4));
        rm1 = fmaxf(rm1, __shfl_xor_sync(0xffffffffu, rm1, 1, 4));
        rm1 = fmaxf(rm1, __shfl_xor_sync(0xffffffffu, rm1, 2, 4));

        float mn0 = fmaxf(m0, rm0), mn1 = fmaxf(m1, rm1);
        float a0 = __expf(m0 - mn0), a1 = __expf(m1 - mn1);
        m0 = mn0; m1 = mn1;
        float rs0 = 0.f, rs1 = 0.f;
#pragma unroll
        for (int nt = 0; nt < 8; nt++) {
            float p0 = __expf(sacc[nt][0] - mn0);
            float p1 = __expf(sacc[nt][1] - mn0);
            float p2 = __expf(sacc[nt][2] - mn1);
            float p3 = __expf(sacc[nt][3] - mn1);
            sacc[nt][0] = p0; sacc[nt][1] = p1;
            sacc[nt][2] = p2; sacc[nt][3] = p3;
            rs0 += p0 + p1; rs1 += p2 + p3;
        }
        rs0 += __shfl_xor_sync(0xffffffffu, rs0, 1, 4);
        rs0 += __shfl_xor_sync(0xffffffffu, rs0, 2, 4);
        rs1 += __shfl_xor_sync(0xffffffffu, rs1, 1, 4);
        rs1 += __shfl_xor_sync(0xffffffffu, rs1, 2, 4);
        l0 = l0*a0 + rs0; l1 = l1*a1 + rs1;
#pragma unroll
        for (int nt = 0; nt < 8; nt++) {
            o[nt][0] *= a0; o[nt][1] *= a0;
            o[nt][2] *= a1; o[nt][3] *= a1;
        }

#pragma unroll
        for (int k4 = 0; k4 < 4; k4++) {
            unsigned pah[4], pal[4];
            float* c0 = sacc[2*k4];
            float* c1 = sacc[2*k4 + 1];
            pah[0] = pack2(c0[0], c0[1]);
            pah[1] = pack2(c0[2], c0[3]);
            pah[2] = pack2(c1[0], c1[1]);
            pah[3] = pack2(c1[2], c1[3]);
            {
                __nv_bfloat162 t0 = *(__nv_bfloat162*)&pah[0];
                __nv_bfloat162 t1 = *(__nv_bfloat162*)&pah[1];
                __nv_bfloat162 t2 = *(__nv_bfloat162*)&pah[2];
                __nv_bfloat162 t3 = *(__nv_bfloat162*)&pah[3];
                pal[0] = pack2(c0[0]-__low2float(t0), c0[1]-__high2float(t0));
                pal[1] = pack2(c0[2]-__low2float(t1), c0[3]-__high2float(t1));
                pal[2] = pack2(c1[0]-__low2float(t2), c1[1]-__high2float(t2));
                pal[3] = pack2(c1[2]-__low2float(t3), c1[3]-__high2float(t3));
            }
            unsigned Vbh[4][4], Vbl[4][4];
#pragma unroll
            for (int p = 0; p < 4; p++) {
                ldsm4(Vbh[p], vH + foff + p*2304 + k4*32);
                ldsm4(Vbl[p], vL + foff + p*2304 + k4*32);
            }
#pragma unroll
            for (int p = 0; p < 4; p++)
#pragma unroll
                for (int sub = 0; sub < 2; sub++) {
                    unsigned bh[2] = {Vbh[p][sub], Vbh[p][sub+2]};
                    mma16816(o[p*2 + sub], pah, bh);
                }
#pragma unroll
            for (int p = 0; p < 4; p++)
#pragma unroll
                for (int sub = 0; sub < 2; sub++) {
                    unsigned bl[2] = {Vbl[p][sub], Vbl[p][sub+2]};
                    mma16816(o[p*2 + sub], pah, bl);
                }
#pragma unroll
            for (int p = 0; p < 4; p++)
#pragma unroll
                for (int sub = 0; sub < 2; sub++) {
                    unsigned bh[2] = {Vbh[p][sub], Vbh[p][sub+2]};
                    mma16816(o[p*2 + sub], pal, bh);
                }
        }
    }

    int b = bh >> 4, h = bh & 15;
    float inv0 = 1.f / l0, inv1 = 1.f / l1;
#pragma unroll
    for (int nt = 0; nt < 8; nt++) {
        int col = h*DKn + nt*8 + t4*2;
        size_t off0 = ((size_t)b*Sn + row0)*Dn + col;
        size_t off1 = ((size_t)b*Sn + row1)*Dn + col;
        store_split(OHsplit, OLsplit, off0, o[nt][0]*inv0, o[nt][1]*inv0);
        store_split(OHsplit, OLsplit, off1, o[nt][2]*inv1, o[nt][3]*inv1);
    }
}

// ---------------------------------------------------------------------------
extern "C" void kernel_launch(void* const* d_in, const int* in_sizes, int n_in,
                              void* d_out, int out_size) {
    const float* x  = (const float*)d_in[0];
    const float* wq = (const float*)d_in[2];
    const float* wk = (const float*)d_in[3];
    const float* wv = (const float*)d_in[4];
    const float* wo = (const float*)d_in[5];
    float* out = (float*)d_out;

    float *cs;
    __nv_bfloat16 *ah, *al, *wh, *wl, *qh, *ql, *kh, *kl, *vh, *vl;
    cudaGetSymbolAddress((void**)&cs, g_cs);
    cudaGetSymbolAddress((void**)&ah, g_ah);
    cudaGetSymbolAddress((void**)&al, g_al);
    cudaGetSymbolAddress((void**)&wh, g_wh);
    cudaGetSymbolAddress((void**)&wl, g_wl);
    cudaGetSymbolAddress((void**)&qh, g_qh);
    cudaGetSymbolAddress((void**)&ql, g_ql);
    cudaGetSymbolAddress((void**)&kh, g_kh);
    cudaGetSymbolAddress((void**)&kl, g_kl);
    cudaGetSymbolAddress((void**)&vh, g_vh);
    cudaGetSymbolAddress((void**)&vl, g_vl);

    static bool attr_set = false;
    if (!attr_set) {
        cudaFuncSetAttribute(gemm_qkv,
                             cudaFuncAttributeMaxDynamicSharedMemorySize, GSMEM);
        cudaFuncSetAttribute(gemm_out,
                             cudaFuncAttributeMaxDynamicSharedMemorySize, GSMEM);
        cudaFuncSetAttribute(attn_mma,
                             cudaFuncAttributeMaxDynamicSharedMemorySize, AGSMEM);
        attr_set = true;
    }

    prep_kernel<<<PREP_BLOCKS, 256>>>(x, wq, wk, wv, wo, cs, ah, al, wh, wl);

    gemm_qkv<<<dim3(48, Mn/128), 256, GSMEM>>>(ah, al, wh, wl, cs,
                                               qh, ql, kh, kl, vh, vl);

    attn_mma<<<dim3(Bn*Hn, Sn/128), 256, AGSMEM>>>(qh, ql, kh, kl, vh, vl, ah, al);

    gemm_out<<<dim3(Dn/64, Mn/128), 256, GSMEM>>>(ah, al, wh + 3*WSZ, wl + 3*WSZ, out);
}

// round 17
// speedup vs baseline: 1.0452x; 1.0173x over previous
#include <cuda_runtime.h>
#include <cuda_bf16.h>
#include <math.h>
#include <stdint.h>

#define Bn 4
#define Sn 2048
#define Dn 1024
#define Hn 16
#define DKn 64
#define Mn (Bn*Sn)
#define WSZ ((size_t)Dn*Dn)

// Scratch (static device globals: allocation-free)
__device__ float g_cs[(size_t)Sn*32*2];                 // cos/sin table
__device__ __nv_bfloat16 g_ah[(size_t)Mn*Dn];
__device__ __nv_bfloat16 g_al[(size_t)Mn*Dn];
__device__ __nv_bfloat16 g_wh[4*WSZ];                   // [wq|wk|wv|wo] hi
__device__ __nv_bfloat16 g_wl[4*WSZ];                   // [wq|wk|wv|wo] lo
__device__ __nv_bfloat16 g_qh[(size_t)Bn*Hn*Sn*DKn];
__device__ __nv_bfloat16 g_ql[(size_t)Bn*Hn*Sn*DKn];
__device__ __nv_bfloat16 g_kh[(size_t)Bn*Hn*Sn*DKn];
__device__ __nv_bfloat16 g_kl[(size_t)Bn*Hn*Sn*DKn];
__device__ __nv_bfloat16 g_vh[(size_t)Bn*Hn*Sn*DKn];   // [bh][dk][s] transposed
__device__ __nv_bfloat16 g_vl[(size_t)Bn*Hn*Sn*DKn];

// ===========================================================================
// helpers
// ===========================================================================
__device__ __forceinline__ uint32_t smem_u32(const void* p) {
    uint32_t a;
    asm("{ .reg .u64 t; cvta.to.shared.u64 t, %1; cvt.u32.u64 %0, t; }"
        : "=r"(a) : "l"(p));
    return a;
}

__device__ __forceinline__ void cpasync16(uint32_t dst, const void* src) {
    asm volatile("cp.async.cg.shared.global [%0], [%1], 16;" :: "r"(dst), "l"(src));
}

__device__ __forceinline__ void ldsm4(unsigned* r, uint32_t addr) {
    asm volatile("ldmatrix.sync.aligned.m8n8.x4.shared.b16 {%0,%1,%2,%3}, [%4];"
                 : "=r"(r[0]), "=r"(r[1]), "=r"(r[2]), "=r"(r[3]) : "r"(addr));
}

__device__ __forceinline__ void mma16816(float* c, const unsigned* a, const unsigned* b) {
    asm volatile(
        "mma.sync.aligned.m16n8k16.row.col.f32.bf16.bf16.f32 "
        "{%0,%1,%2,%3}, {%4,%5,%6,%7}, {%8,%9}, {%0,%1,%2,%3};"
        : "+f"(c[0]), "+f"(c[1]), "+f"(c[2]), "+f"(c[3])
        : "r"(a[0]), "r"(a[1]), "r"(a[2]), "r"(a[3]), "r"(b[0]), "r"(b[1]));
}

__device__ __forceinline__ unsigned pack2(float x, float y) {
    __nv_bfloat162 t = __floats2bfloat162_rn(x, y);
    return *(unsigned*)&t;
}

__device__ __forceinline__ void store_split(__nv_bfloat16* H, __nv_bfloat16* L,
                                            size_t off, float a, float b) {
    unsigned hp = pack2(a, b);
    __nv_bfloat162 ht = *(__nv_bfloat162*)&hp;
    unsigned lp = pack2(a - __low2float(ht), b - __high2float(ht));
    *(unsigned*)(H + off) = hp;
    *(unsigned*)(L + off) = lp;
}

// XOR-swizzled offset within a 64B-row array: row, 16B-chunk kc (0..3)
__device__ __forceinline__ uint32_t swz64(uint32_t row, uint32_t kc) {
    return (row << 6) + ((kc ^ ((row >> 1) & 3u)) << 4);
}

// ===========================================================================
// Fused preprocessing: x split | 4 weight splits | trig table. One launch.
// ===========================================================================
#define PB_X 8192
#define PB_W 4096
#define PB_T 256
#define PREP_BLOCKS (PB_X + PB_W + PB_T)

__device__ __forceinline__ void split4(const float* __restrict__ in, size_t i,
                                       __nv_bfloat16* __restrict__ hi,
                                       __nv_bfloat16* __restrict__ lo, size_t off) {
    float4 v = *(const float4*)(in + 4*i);
    __nv_bfloat16 h0 = __float2bfloat16(v.x);
    __nv_bfloat16 h1 = __float2bfloat16(v.y);
    __nv_bfloat16 h2 = __float2bfloat16(v.z);
    __nv_bfloat16 h3 = __float2bfloat16(v.w);
    __nv_bfloat16 l0 = __float2bfloat16(v.x - __bfloat162float(h0));
    __nv_bfloat16 l1 = __float2bfloat16(v.y - __bfloat162float(h1));
    __nv_bfloat16 l2 = __float2bfloat16(v.z - __bfloat162float(h2));
    __nv_bfloat16 l3 = __float2bfloat16(v.w - __bfloat162float(h3));
    __nv_bfloat162* ph = (__nv_bfloat162*)(hi + off);
    __nv_bfloat162* pl = (__nv_bfloat162*)(lo + off);
    ph[0] = __nv_bfloat162(h0, h1); ph[1] = __nv_bfloat162(h2, h3);
    pl[0] = __nv_bfloat162(l0, l1); pl[1] = __nv_bfloat162(l2, l3);
}

__global__ void prep_kernel(const float* __restrict__ x,
                            const float* __restrict__ wq, const float* __restrict__ wk,
                            const float* __restrict__ wv, const float* __restrict__ wo,
                            float* __restrict__ cs,
                            __nv_bfloat16* __restrict__ ah, __nv_bfloat16* __restrict__ al,
                            __nv_bfloat16* __restrict__ wh, __nv_bfloat16* __restrict__ wl) {
    int blk = blockIdx.x;
    if (blk < PB_X) {
        size_t i = (size_t)blk * 256 + threadIdx.x;
        split4(x, i, ah, al, 4*i);
    } else if (blk < PB_X + PB_W) {
        int r = blk - PB_X;
        int which = r >> 10;
        size_t i = (size_t)(r & 1023) * 256 + threadIdx.x;
        const float* in = which == 0 ? wq : which == 1 ? wk : which == 2 ? wv : wo;
        split4(in, i, wh, wl, (size_t)which * WSZ + 4*i);
    } else {
        int p = (blk - PB_X - PB_W) * 256 + threadIdx.x;
        if (p < Sn*32) {
            int s = p >> 5, i = p & 31;
            float freq = expf(-((float)(2*i) / (float)DKn) * 9.210340371976184f);
            float sn, c;
            sincosf((float)s * freq, &sn, &c);
            cs[p*2]   = c;
            cs[p*2+1] = sn;
        }
    }
}

// ===========================================================================
// Split-bf16 GEMM core. 64x64 tile, BK=32, 256 thr, 4 CTAs/SM target.
// 8 warps (4m x 2n), warp tile 16x32. XOR-swizzled smem, 3-stage ring,
// mid-stage cp.async issue.
// ===========================================================================
#define A_SZ 4096              // 64 rows * 64 B
#define STG (4*A_SZ)           // Ah,Al,Wh,Wl = 16384
#define NST 3
#define GSMEM (NST*STG)        // 49152 -> 4 CTAs/SM (192KB)

__device__ __forceinline__ void gemm_load_stage(
    uint32_t sbase, int s, int tid, int mbase, int nbase,
    const __nv_bfloat16* __restrict__ Ah, const __nv_bfloat16* __restrict__ Al,
    const __nv_bfloat16* __restrict__ Wh, const __nv_bfloat16* __restrict__ Wl) {
    uint32_t sb = sbase + (uint32_t)(s % NST) * STG;
    int k0 = s * 32;
    uint32_t row = (uint32_t)tid >> 2;
    uint32_t kc = (uint32_t)tid & 3;
    uint32_t so = swz64(row, kc);
    size_t ga = (size_t)(mbase + (int)row) * Dn + k0 + (int)kc * 8;
    size_t gw = (size_t)(nbase + (int)row) * Dn + k0 + (int)kc * 8;
    cpasync16(sb + so,          Ah + ga);
    cpasync16(sb + A_SZ + so,   Al + ga);
    cpasync16(sb + 2*A_SZ + so, Wh + gw);
    cpasync16(sb + 3*A_SZ + so, Wl + gw);
    asm volatile("cp.async.commit_group;" ::: "memory");
}

// one k16 chunk: ldsm + 3 term-major passes (12 MMAs)
__device__ __forceinline__ void gemm_chunk(
    uint32_t aH, uint32_t aL, uint32_t bH, uint32_t bL,
    uint32_t kc, uint32_t r15, int wm, int wn, float acc[4][4]) {
    unsigned Af[4], Bh2[2][4], Bl2[2][4];
    ldsm4(Af, aH + swz64((uint32_t)wm + r15, kc));
#pragma unroll
    for (int p = 0; p < 2; p++) {
        uint32_t br = (uint32_t)(wn + p*16) + r15;
        ldsm4(Bh2[p], bH + swz64(br, kc));
        ldsm4(Bl2[p], bL + swz64(br, kc));
    }
    // pass 1: Ah*Wh (4 independent accumulators)
#pragma unroll
    for (int p = 0; p < 2; p++)
#pragma unroll
        for (int sub = 0; sub < 2; sub++) {
            unsigned bh[2] = {Bh2[p][sub], Bh2[p][sub+2]};
            mma16816(acc[p*2 + sub], Af, bh);
        }
    // pass 2: Ah*Wl
#pragma unroll
    for (int p = 0; p < 2; p++)
#pragma unroll
        for (int sub = 0; sub < 2; sub++) {
            unsigned bl[2] = {Bl2[p][sub], Bl2[p][sub+2]};
            mma16816(acc[p*2 + sub], Af, bl);
        }
    // reload A-lo into the SAME registers
    ldsm4(Af, aL + swz64((uint32_t)wm + r15, kc));
    // pass 3: Al*Wh
#pragma unroll
    for (int p = 0; p < 2; p++)
#pragma unroll
        for (int sub = 0; sub < 2; sub++) {
            unsigned bh[2] = {Bh2[p][sub], Bh2[p][sub+2]};
            mma16816(acc[p*2 + sub], Af, bh);
        }
}

__device__ __forceinline__ void gemm_mainloop(
    uint32_t sbase, int tid, int mbase, int nbase,
    const __nv_bfloat16* __restrict__ Ah, const __nv_bfloat16* __restrict__ Al,
    const __nv_bfloat16* __restrict__ Wh, const __nv_bfloat16* __restrict__ Wl,
    float acc[4][4]) {
    int wid = tid >> 5, lane = tid & 31;
    int wm = (wid >> 1) * 16;
    int wn = (wid & 1) * 32;
    uint32_t r15 = (uint32_t)(lane & 15);
    uint32_t hi  = (uint32_t)(lane >> 4);

#pragma unroll
    for (int ni = 0; ni < 4; ni++)
#pragma unroll
        for (int e = 0; e < 4; e++) acc[ni][e] = 0.f;

    gemm_load_stage(sbase, 0, tid, mbase, nbase, Ah, Al, Wh, Wl);
    gemm_load_stage(sbase, 1, tid, mbase, nbase, Ah, Al, Wh, Wl);

    for (int s = 0; s < 32; s++) {
        if (s + 1 < 32)
            asm volatile("cp.async.wait_group 1;" ::: "memory");
        else
            asm volatile("cp.async.wait_group 0;" ::: "memory");
        __syncthreads();

        uint32_t sb = sbase + (uint32_t)(s % NST) * STG;
        uint32_t aH = sb, aL = sb + A_SZ;
        uint32_t bH = sb + 2*A_SZ, bL = sb + 3*A_SZ;

        gemm_chunk(aH, aL, bH, bL, hi + 0, r15, wm, wn, acc);
        if (s + 2 < 32)
            gemm_load_stage(sbase, s + 2, tid, mbase, nbase, Ah, Al, Wh, Wl);
        gemm_chunk(aH, aL, bH, bL, hi + 2, r15, wm, wn, acc);
    }
}

// ---------------------------------------------------------------------------
// Fused QKV projection. grid (48, 128): proj = bx>>4, nb = bx&15 (64-wide),
// mbase = by*64.
// ---------------------------------------------------------------------------
__global__ __launch_bounds__(256, 4) void gemm_qkv(
    const __nv_bfloat16* __restrict__ Ah, const __nv_bfloat16* __restrict__ Al,
    const __nv_bfloat16* __restrict__ Whal, const __nv_bfloat16* __restrict__ Wlal,
    const float* __restrict__ cs,
    __nv_bfloat16* __restrict__ QH, __nv_bfloat16* __restrict__ QL,
    __nv_bfloat16* __restrict__ KH, __nv_bfloat16* __restrict__ KL,
    __nv_bfloat16* __restrict__ VH, __nv_bfloat16* __restrict__ VL) {
    extern __shared__ __align__(16) char dyn[];
    uint32_t sbase = smem_u32(dyn);
    int tid = threadIdx.x;
    int proj = blockIdx.x >> 4;
    int nbase = (blockIdx.x & 15) * 64;
    int mbase = blockIdx.y * 64;

    const __nv_bfloat16* Wh = Whal + (size_t)proj * WSZ;
    const __nv_bfloat16* Wl = Wlal + (size_t)proj * WSZ;

    float acc[4][4];
    gemm_mainloop(sbase, tid, mbase, nbase, Ah, Al, Wh, Wl, acc);

    int wid = tid >> 5, lane = tid & 31;
    int grp = lane >> 2, t4 = lane & 3;
    int wm = (wid >> 1) * 16, wn = (wid & 1) * 32;

    if (proj == 2) {
        __syncthreads();
        float* st = (float*)dyn;               // [col][row], pitch 65
#pragma unroll
        for (int ni = 0; ni < 4; ni++) {
            int r0 = wm + grp;
            int c  = wn + ni*8 + t4*2;
            st[(c  )*65 + r0    ] = acc[ni][0];
            st[(c+1)*65 + r0    ] = acc[ni][1];
            st[(c  )*65 + r0 + 8] = acc[ni][2];
            st[(c+1)*65 + r0 + 8] = acc[ni][3];
        }
        __syncthreads();
        int c  = tid >> 2;                     // 0..63 (dk within tile)
        int sh = (tid & 3) * 16;               // s-sixteenth
        int gcol = nbase + c;
        int h = gcol >> 6, dk = gcol & 63;
        int b = mbase >> 11, sq = mbase & (Sn-1);
        size_t base = ((size_t)((b*Hn + h)*64) + dk)*Sn + sq + sh;
        const float* row = st + c*65 + sh;
#pragma unroll
        for (int j = 0; j < 2; j++) {
            uint32_t hv[4], lv[4];
#pragma unroll
            for (int i = 0; i < 4; i++) {
                float a = row[j*8 + 2*i], bb = row[j*8 + 2*i + 1];
                hv[i] = pack2(a, bb);
                __nv_bfloat162 ht = *(__nv_bfloat162*)&hv[i];
                lv[i] = pack2(a - __low2float(ht), bb - __high2float(ht));
            }
            *(uint4*)(VH + base + j*8) = make_uint4(hv[0], hv[1], hv[2], hv[3]);
            *(uint4*)(VL + base + j*8) = make_uint4(lv[0], lv[1], lv[2], lv[3]);
        }
        return;
    }

    __nv_bfloat16* OH = (proj == 0) ? QH : KH;
    __nv_bfloat16* OL = (proj == 0) ? QL : KL;
#pragma unroll
    for (int ni = 0; ni < 4; ni++) {
        int row0 = mbase + wm + grp;
        int row1 = row0 + 8;
        int col  = nbase + wn + ni*8 + t4*2;
        int h = col >> 6;
        int d = col & 63;
        int i = d >> 1;
        int s0 = row0 & (Sn-1), b0 = row0 >> 11;
        int s1 = row1 & (Sn-1), b1 = row1 >> 11;
        float2 c0 = *(const float2*)(cs + ((size_t)s0*32 + i)*2);
        float2 c1 = *(const float2*)(cs + ((size_t)s1*32 + i)*2);
        float r00 = acc[ni][0]*c0.x - acc[ni][1]*c0.y;
        float r01 = acc[ni][0]*c0.y + acc[ni][1]*c0.x;
        float r10 = acc[ni][2]*c1.x - acc[ni][3]*c1.y;
        float r11 = acc[ni][2]*c1.y + acc[ni][3]*c1.x;
        size_t off0 = ((size_t)(b0*Hn + h)*Sn + s0)*DKn + d;
        size_t off1 = ((size_t)(b1*Hn + h)*Sn + s1)*DKn + d;
        store_split(OH, OL, off0, r00, r01);
        store_split(OH, OL, off1, r10, r11);
    }
}

// ---------------------------------------------------------------------------
// Output projection: plain fp32 epilogue. grid (16, 128).
// ---------------------------------------------------------------------------
__global__ __launch_bounds__(256, 4) void gemm_out(
    const __nv_bfloat16* __restrict__ Ah, const __nv_bfloat16* __restrict__ Al,
    const __nv_bfloat16* __restrict__ Wh, const __nv_bfloat16* __restrict__ Wl,
    float* __restrict__ C) {
    extern __shared__ __align__(16) char dyn[];
    uint32_t sbase = smem_u32(dyn);
    int tid = threadIdx.x;
    int mbase = blockIdx.y * 64, nbase = blockIdx.x * 64;

    float acc[4][4];
    gemm_mainloop(sbase, tid, mbase, nbase, Ah, Al, Wh, Wl, acc);

    int wid = tid >> 5, lane = tid & 31;
    int grp = lane >> 2, t4 = lane & 3;
    int wm = (wid >> 1) * 16, wn = (wid & 1) * 32;
#pragma unroll
    for (int ni = 0; ni < 4; ni++) {
        int row0 = mbase + wm + grp;
        int col  = nbase + wn + ni*8 + t4*2;
        *(float2*)(C + (size_t)row0 * Dn + col) =
            make_float2(acc[ni][0], acc[ni][1]);
        *(float2*)(C + (size_t)(row0+8) * Dn + col) =
            make_float2(acc[ni][2], acc[ni][3]);
    }
}

// ---------------------------------------------------------------------------
// Causal flash attention, split-bf16 MMA + ldmatrix, term-major MMA order.
// 3-stage cp.async ring (wait lag 1), next-tile load issued after QK MMAs.
// grid (bh=64, qtrev=16). (unchanged from R16)
// ---------------------------------------------------------------------------
#define LDA 72        // halfs; byte pitch 144
#define AARR 9216     // one array: 64 rows * 144 B
#define ASTG (4*AARR)    // stage: Kh,Kl,Vh,Vl = 36864
#define ANST 3
#define AGSMEM (ANST*ASTG)  // 110592 -> 2 CTAs/SM

__device__ __forceinline__ void attn_load_tile(
    uint32_t sb, int bh, int kbase, int lr, int lc,
    const __nv_bfloat16* __restrict__ Kh, const __nv_bfloat16* __restrict__ Kl,
    const __nv_bfloat16* __restrict__ Vh, const __nv_bfloat16* __restrict__ Vl) {
#pragma unroll
    for (int rr = 0; rr < 2; rr++) {
        int row = lr + rr*32;
        uint32_t so = (uint32_t)row * 144 + (uint32_t)lc * 2;
        size_t koff = ((size_t)bh*Sn + kbase + row)*DKn + lc;
        size_t voff = ((size_t)bh*64 + row)*Sn + kbase + lc;
        cpasync16(sb + so,          Kh + koff);
        cpasync16(sb + AARR + so,   Kl + koff);
        cpasync16(sb + 2*AARR + so, Vh + voff);
        cpasync16(sb + 3*AARR + so, Vl + voff);
    }
    asm volatile("cp.async.commit_group;" ::: "memory");
}

__global__ __launch_bounds__(256, 2) void attn_mma(
    const __nv_bfloat16* __restrict__ Qh, const __nv_bfloat16* __restrict__ Ql,
    const __nv_bfloat16* __restrict__ Kh, const __nv_bfloat16* __restrict__ Kl,
    const __nv_bfloat16* __restrict__ Vh, const __nv_bfloat16* __restrict__ Vl,
    __nv_bfloat16* __restrict__ OHsplit, __nv_bfloat16* __restrict__ OLsplit) {
    extern __shared__ __align__(16) char adyn[];
    uint32_t sb0 = smem_u32(adyn);

    int tid = threadIdx.x;
    int wid = tid >> 5, lane = tid & 31;
    int grp = lane >> 2, t4 = lane & 3;
    int bh = blockIdx.x;
    int qt = (int)gridDim.y - 1 - (int)blockIdx.y;   // fat blocks first
    int qbase = qt * 128;
    int lr = tid >> 3;
    int lc = (tid & 7) * 8;

    uint32_t foff = (uint32_t)(lane & 15) * 144 + (lane >> 4) * 16;

    // ---- Stage Q fragments (reuse stage-0 K buffers, sync loads) ----
    unsigned qfh[4][4], qfl[4][4];
#pragma unroll
    for (int half = 0; half < 2; half++) {
        const __nv_bfloat16* qsh = Qh + ((size_t)bh*Sn + qbase + half*64)*DKn;
        const __nv_bfloat16* qsl = Ql + ((size_t)bh*Sn + qbase + half*64)*DKn;
#pragma unroll
        for (int rr = 0; rr < 2; rr++) {
            int row = lr + rr*32;
            uint32_t so = (uint32_t)row * 144 + (uint32_t)lc * 2;
            *(uint4*)(adyn + so)        = *(const uint4*)(qsh + row*DKn + lc);
            *(uint4*)(adyn + AARR + so) = *(const uint4*)(qsl + row*DKn + lc);
        }
        __syncthreads();
        if ((wid >> 2) == half) {
            uint32_t qoff = (uint32_t)((wid & 3)*16 + (lane & 15)) * 144 + (lane >> 4) * 16;
#pragma unroll
            for (int k4 = 0; k4 < 4; k4++) {
                ldsm4(qfh[k4], sb0 + qoff + k4*32);
                ldsm4(qfl[k4], sb0 + AARR + qoff + k4*32);
            }
        }
        __syncthreads();
    }

    int row0 = qbase + wid*16 + grp;
    int row1 = row0 + 8;
    float o[8][4];
    float m0 = -1e30f, m1 = -1e30f, l0 = 0.f, l1 = 0.f;
#pragma unroll
    for (int nt = 0; nt < 8; nt++)
#pragma unroll
        for (int e = 0; e < 4; e++) o[nt][e] = 0.f;

    const float SCALE = 0.125f;
    int ktmax = 2*qt + 2;   // always >= 2

    // preload tiles 0 and 1 (stages 0, 1)
    attn_load_tile(sb0, bh, 0, lr, lc, Kh, Kl, Vh, Vl);
    attn_load_tile(sb0 + ASTG, bh, 64, lr, lc, Kh, Kl, Vh, Vl);

    for (int kt = 0; kt < ktmax; kt++) {
        int kbase = kt * 64;
        if (kt + 1 < ktmax)
            asm volatile("cp.async.wait_group 1;" ::: "memory");
        else
            asm volatile("cp.async.wait_group 0;" ::: "memory");
        __syncthreads();

        uint32_t sb = sb0 + (uint32_t)(kt % ANST) * ASTG;
        uint32_t kH = sb, kL = sb + AARR, vH = sb + 2*AARR, vL = sb + 3*AARR;

        float sacc[8][4];
#pragma unroll
        for (int nt = 0; nt < 8; nt++)
#pragma unroll
            for (int e = 0; e < 4; e++) sacc[nt][e] = 0.f;

#pragma unroll
        for (int k4 = 0; k4 < 4; k4++) {
            unsigned Bh[4][4], Bl[4][4];
#pragma unroll
            for (int p = 0; p < 4; p++) {
                ldsm4(Bh[p], kH + foff + p*2304 + k4*32);
                ldsm4(Bl[p], kL + foff + p*2304 + k4*32);
            }
#pragma unroll
            for (int p = 0; p < 4; p++)
#pragma unroll
                for (int sub = 0; sub < 2; sub++) {
                    unsigned bh[2] = {Bh[p][sub], Bh[p][sub+2]};
                    mma16816(sacc[p*2 + sub], qfh[k4], bh);
                }
#pragma unroll
            for (int p = 0; p < 4; p++)
#pragma unroll
                for (int sub = 0; sub < 2; sub++) {
                    unsigned bl[2] = {Bl[p][sub], Bl[p][sub+2]};
                    mma16816(sacc[p*2 + sub], qfh[k4], bl);
                }
#pragma unroll
            for (int p = 0; p < 4; p++)
#pragma unroll
                for (int sub = 0; sub < 2; sub++) {
                    unsigned bh[2] = {Bh[p][sub], Bh[p][sub+2]};
                    mma16816(sacc[p*2 + sub], qfl[k4], bh);
                }
        }

        // issue tile kt+2's loads: overlaps softmax + PV below.
        if (kt + 2 < ktmax)
            attn_load_tile(sb0 + (uint32_t)((kt + 2) % ANST) * ASTG, bh,
                           kbase + 128, lr, lc, Kh, Kl, Vh, Vl);

        bool diag = (kbase + 64 > qbase + wid*16);
        float rm0 = -1e30f, rm1 = -1e30f;
#pragma unroll
        for (int nt = 0; nt < 8; nt++) {
            int key = kbase + nt*8 + t4*2;
            float s0 = sacc[nt][0]*SCALE, s1 = sacc[nt][1]*SCALE;
            float s2 = sacc[nt][2]*SCALE, s3 = sacc[nt][3]*SCALE;
            if (diag) {
                if (key     > row0) s0 = -1e30f;
                if (key + 1 > row0) s1 = -1e30f;
                if (key     > row1) s2 = -1e30f;
                if (key + 1 > row1) s3 = -1e30f;
            }
            sacc[nt][0] = s0; sacc[nt][1] = s1;
            sacc[nt][2] = s2; sacc[nt][3] = s3;
            rm0 = fmaxf(rm0, fmaxf(s0, s1));
            rm1 = fmaxf(rm1, fmaxf(s2, s3));
        }
        rm0 = fmaxf(rm0, __shfl_xor_sync(0xffffffffu, rm0, 1, 4));
        rm0 = fmaxf(rm0, __shfl_xor_sync(0xffffffffu, rm0, 2, 4));
        rm1 = fmaxf(rm1, __shfl_xor_sync(0xffffffffu, rm1, 1, 4));
        rm1 = fmaxf(rm1, __shfl_xor_sync(0xffffffffu, rm1, 2, 4));

        float mn0 = fmaxf(m0, rm0), mn1 = fmaxf(m1, rm1);
        float a0 = __expf(m0 - mn0), a1 = __expf(m1 - mn1);
        m0 = mn0; m1 = mn1;
        float rs0 = 0.f, rs1 = 0.f;
#pragma unroll
        for (int nt = 0; nt < 8; nt++) {
            float p0 = __expf(sacc[nt][0] - mn0);
            float p1 = __expf(sacc[nt][1] - mn0);
            float p2 = __expf(sacc[nt][2] - mn1);
            float p3 = __expf(sacc[nt][3] - mn1);
            sacc[nt][0] = p0; sacc[nt][1] = p1;
            sacc[nt][2] = p2; sacc[nt][3] = p3;
            rs0 += p0 + p1; rs1 += p2 + p3;
        }
        rs0 += __shfl_xor_sync(0xffffffffu, rs0, 1, 4);
        rs0 += __shfl_xor_sync(0xffffffffu, rs0, 2, 4);
        rs1 += __shfl_xor_sync(0xffffffffu, rs1, 1, 4);
        rs1 += __shfl_xor_sync(0xffffffffu, rs1, 2, 4);
        l0 = l0*a0 + rs0; l1 = l1*a1 + rs1;
#pragma unroll
        for (int nt = 0; nt < 8; nt++) {
            o[nt][0] *= a0; o[nt][1] *= a0;
            o[nt][2] *= a1; o[nt][3] *= a1;
        }

#pragma unroll
        for (int k4 = 0; k4 < 4; k4++) {
            unsigned pah[4], pal[4];
            float* c0 = sacc[2*k4];
            float* c1 = sacc[2*k4 + 1];
            pah[0] = pack2(c0[0], c0[1]);
            pah[1] = pack2(c0[2], c0[3]);
            pah[2] = pack2(c1[0], c1[1]);
            pah[3] = pack2(c1[2], c1[3]);
            {
                __nv_bfloat162 t0 = *(__nv_bfloat162*)&pah[0];
                __nv_bfloat162 t1 = *(__nv_bfloat162*)&pah[1];
                __nv_bfloat162 t2 = *(__nv_bfloat162*)&pah[2];
                __nv_bfloat162 t3 = *(__nv_bfloat162*)&pah[3];
                pal[0] = pack2(c0[0]-__low2float(t0), c0[1]-__high2float(t0));
                pal[1] = pack2(c0[2]-__low2float(t1), c0[3]-__high2float(t1));
                pal[2] = pack2(c1[0]-__low2float(t2), c1[1]-__high2float(t2));
                pal[3] = pack2(c1[2]-__low2float(t3), c1[3]-__high2float(t3));
            }
            unsigned Vbh[4][4], Vbl[4][4];
#pragma unroll
            for (int p = 0; p < 4; p++) {
                ldsm4(Vbh[p], vH + foff + p*2304 + k4*32);
                ldsm4(Vbl[p], vL + foff + p*2304 + k4*32);
            }
#pragma unroll
            for (int p = 0; p < 4; p++)
#pragma unroll
                for (int sub = 0; sub < 2; sub++) {
                    unsigned bh[2] = {Vbh[p][sub], Vbh[p][sub+2]};
                    mma16816(o[p*2 + sub], pah, bh);
                }
#pragma unroll
            for (int p = 0; p < 4; p++)
#pragma unroll
                for (int sub = 0; sub < 2; sub++) {
                    unsigned bl[2] = {Vbl[p][sub], Vbl[p][sub+2]};
                    mma16816(o[p*2 + sub], pah, bl);
                }
#pragma unroll
            for (int p = 0; p < 4; p++)
#pragma unroll
                for (int sub = 0; sub < 2; sub++) {
                    unsigned bh[2] = {Vbh[p][sub], Vbh[p][sub+2]};
                    mma16816(o[p*2 + sub], pal, bh);
                }
        }
    }

    int b = bh >> 4, h = bh & 15;
    float inv0 = 1.f / l0, inv1 = 1.f / l1;
#pragma unroll
    for (int nt = 0; nt < 8; nt++) {
        int col = h*DKn + nt*8 + t4*2;
        size_t off0 = ((size_t)b*Sn + row0)*Dn + col;
        size_t off1 = ((size_t)b*Sn + row1)*Dn + col;
        store_split(OHsplit, OLsplit, off0, o[nt][0]*inv0, o[nt][1]*inv0);
        store_split(OHsplit, OLsplit, off1, o[nt][2]*inv1, o[nt][3]*inv1);
    }
}

// ---------------------------------------------------------------------------
extern "C" void kernel_launch(void* const* d_in, const int* in_sizes, int n_in,
                              void* d_out, int out_size) {
    const float* x  = (const float*)d_in[0];
    const float* wq = (const float*)d_in[2];
    const float* wk = (const float*)d_in[3];
    const float* wv = (const float*)d_in[4];
    const float* wo = (const float*)d_in[5];
    float* out = (float*)d_out;

    float *cs;
    __nv_bfloat16 *ah, *al, *wh, *wl, *qh, *ql, *kh, *kl, *vh, *vl;
    cudaGetSymbolAddress((void**)&cs, g_cs);
    cudaGetSymbolAddress((void**)&ah, g_ah);
    cudaGetSymbolAddress((void**)&al, g_al);
    cudaGetSymbolAddress((void**)&wh, g_wh);
    cudaGetSymbolAddress((void**)&wl, g_wl);
    cudaGetSymbolAddress((void**)&qh, g_qh);
    cudaGetSymbolAddress((void**)&ql, g_ql);
    cudaGetSymbolAddress((void**)&kh, g_kh);
    cudaGetSymbolAddress((void**)&kl, g_kl);
    cudaGetSymbolAddress((void**)&vh, g_vh);
    cudaGetSymbolAddress((void**)&vl, g_vl);

    static bool attr_set = false;
    if (!attr_set) {
        cudaFuncSetAttribute(gemm_qkv,
                             cudaFuncAttributeMaxDynamicSharedMemorySize, GSMEM);
        cudaFuncSetAttribute(gemm_out,
                             cudaFuncAttributeMaxDynamicSharedMemorySize, GSMEM);
        cudaFuncSetAttribute(attn_mma,
                             cudaFuncAttributeMaxDynamicSharedMemorySize, AGSMEM);
        attr_set = true;
    }

    prep_kernel<<<PREP_BLOCKS, 256>>>(x, wq, wk, wv, wo, cs, ah, al, wh, wl);

    gemm_qkv<<<dim3(48, Mn/64), 256, GSMEM>>>(ah, al, wh, wl, cs,
                                              qh, ql, kh, kl, vh, vl);

    attn_mma<<<dim3(Bn*Hn, Sn/128), 256, AGSMEM>>>(qh, ql, kh, kl, vh, vl, ah, al);

    gemm_out<<<dim3(Dn/64, Mn/64), 256, GSMEM>>>(ah, al, wh + 3*WSZ, wl + 3*WSZ, out);
}